// round 9
// baseline (speedup 1.0000x reference)
#include <cuda_runtime.h>
#include <cuda_fp16.h>
#include <cstdint>

// ---------------------------------------------------------------------------
// FCOS head, fp16 mma.sync (m16n8k16, fp32 accum). Level+path batched,
// 4-deep cp.async ring. R8: warp tile 64x64 (4 warps / 128 threads per CTA)
// to halve per-MAC shared-memory fragment traffic vs R6.
// ---------------------------------------------------------------------------

#define TP 20267
#define TOTE 10376704          // total NHWC elements (all levels, both batch)
#define PAD 20                 // smem row pitch in uint32 words
#define NTILES 319             // total M-tiles over all levels
#define STAGE_BYTES 20480      // per pipeline slot: A(10240) + B(10240)
#define DYN_SMEM (4 * STAGE_BYTES)

__device__ __half g_xh[TOTE];
__device__ __half g_actA[TOTE];   // cls ping
__device__ __half g_actB[TOTE];   // cls pong
__device__ __half g_actC[TOTE];   // reg ping
__device__ __half g_actD[TOTE];   // reg pong
__device__ float  g_y[TOTE];      // cls conv out
__device__ float  g_y2[TOTE];     // reg conv out
__device__ float  g_mean[640];
__device__ float  g_inv[640];
__device__ float  g_regw[26 * 256 * 9];
__device__ float  g_regb[26];
__device__ __half g_wt_cls[4 * 9 * 256 * 256];   // [s][tap][oc][ic]
__device__ __half g_wt_reg[4 * 9 * 256 * 256];
__device__ __half g_wtc_out[2 * 9 * 128 * 256];  // [part][tap][ocpad][ic]
__device__ __half g_wtr_out[2 * 9 * 128 * 256];

__constant__ int c_Hs[5] = {100, 50, 25, 13, 7};
__constant__ int c_Ws[5] = {152, 76, 38, 19, 10};
__constant__ int c_HWs[5] = {15200, 3800, 950, 247, 70};
__constant__ int c_Ps[5] = {30400, 7600, 1900, 494, 140};
__constant__ int c_tb[5] = {0, 238, 298, 313, 317};
__constant__ int c_ao[5] = {0, 7782400, 9728000, 10214400, 10340864};
__constant__ int c_lb[5] = {0, 15200, 19000, 19950, 20197};

__constant__ long long c_base[26] = {
    3242720LL, 3242720LL, 3242720LL, 3242720LL,
    3404856LL,
    3445390LL, 3445390LL, 3445390LL,
    3566992LL,
    3607526LL, 3607526LL, 3607526LL, 3607526LL, 3607526LL, 3607526LL,
    3607526LL, 3607526LL, 3607526LL, 3607526LL, 3607526LL, 3607526LL,
    3607526LL, 3607526LL, 3607526LL, 3607526LL,
    4256070LL};
__constant__ int c_ctot[26] = {4, 4, 4, 4, 1, 3, 3, 3, 1,
                               16, 16, 16, 16, 16, 16, 16, 16,
                               16, 16, 16, 16, 16, 16, 16, 16, 1};
__constant__ int c_ch[26] = {0, 1, 2, 3, 0, 0, 1, 2, 0,
                             0, 1, 2, 3, 4, 5, 6, 7,
                             8, 9, 10, 11, 12, 13, 14, 15, 0};
__constant__ int c_relu[26] = {1, 1, 1, 1, 0, 0, 0, 0, 0,
                               0, 0, 0, 0, 0, 0, 0, 0,
                               0, 0, 0, 0, 0, 0, 0, 0, 0};

__device__ __forceinline__ void cpa16p(uint32_t d, const void* s, int sz) {
    asm volatile("cp.async.cg.shared.global [%0], [%1], 16, %2;" ::"r"(d), "l"(s), "r"(sz));
}
#define LDSM4(r0, r1, r2, r3, a)                                           \
    asm volatile("ldmatrix.sync.aligned.m8n8.x4.shared.b16 {%0,%1,%2,%3}, [%4];" \
                 : "=r"(r0), "=r"(r1), "=r"(r2), "=r"(r3) : "r"(a))

// ---------------------------------------------------------------------------
// NCHW fp32 -> NHWC half, all levels in one launch. grid (475, 8, 10)
// ---------------------------------------------------------------------------
__global__ void to_nhwc_half(const float* __restrict__ f0, const float* __restrict__ f1,
                             const float* __restrict__ f2, const float* __restrict__ f3,
                             const float* __restrict__ f4, __half* __restrict__ xh) {
    __shared__ float t[32][33];
    int z = blockIdx.z;
    int lvl = z >> 1, n = z & 1;
    int HW = c_HWs[lvl];
    int p0 = blockIdx.x * 32;
    if (p0 >= HW) return;
    const float* src = lvl == 0 ? f0 : lvl == 1 ? f1 : lvl == 2 ? f2 : lvl == 3 ? f3 : f4;
    __half* dst = xh + c_ao[lvl];
    int c0 = blockIdx.y * 32;
    int tx = threadIdx.x, ty = threadIdx.y;
    int p = p0 + tx;
    if (p < HW) t[ty][tx] = src[((size_t)(n * 256 + c0 + ty)) * HW + p];
    __syncthreads();
    int p2 = p0 + ty, c2 = c0 + tx;
    if (p2 < HW) dst[((size_t)(n * HW + p2)) * 256 + c2] = __float2half_rn(t[tx][ty]);
}

// ---------------------------------------------------------------------------
// Weight packs
// ---------------------------------------------------------------------------
__global__ void pack_wt(const float* __restrict__ w, __half* __restrict__ wt) {
    int idx = blockIdx.x * blockDim.x + threadIdx.x;
    if (idx >= 4 * 9 * 256 * 256) return;
    int ic = idx & 255;
    int oc = (idx >> 8) & 255;
    int tap = (idx >> 16) % 9;
    int s = idx / 589824;
    wt[idx] = __float2half_rn(w[(((size_t)(s * 256 + oc) * 256 + ic) * 9) + tap]);
}

__global__ void pack_headw(const float* __restrict__ src, __half* __restrict__ dst,
                           int OC) {
    int idx = blockIdx.x * blockDim.x + threadIdx.x;
    if (idx >= 2 * 9 * 128 * 256) return;
    int ic = idx & 255;
    int oc = (idx >> 8) & 127;
    int tap = (idx >> 15) % 9;
    int part = idx / (9 * 128 * 256);
    float v = 0.f;
    if (oc < OC) v = src[((size_t)oc * 256 + ic) * 9 + tap];
    __half hi = __float2half_rn(v);
    dst[idx] = (part == 0) ? hi : __float2half_rn(v - __half2float(hi));
}

__global__ void pack_reg(const float* __restrict__ bbox_w, const float* __restrict__ bbox_b,
                         const float* __restrict__ ctr_w,  const float* __restrict__ ctr_b,
                         const float* __restrict__ dim_w,  const float* __restrict__ dim_b,
                         const float* __restrict__ ori_w,  const float* __restrict__ ori_b,
                         const float* __restrict__ kp_w,   const float* __restrict__ kp_b,
                         const float* __restrict__ depth_w,const float* __restrict__ depth_b) {
    int idx = blockIdx.x * blockDim.x + threadIdx.x;
    int total = 26 * 2304;
    if (idx < total) {
        int oc = idx / 2304;
        int r = idx % 2304;
        const float* src;
        if (oc < 4)       src = bbox_w + oc * 2304;
        else if (oc == 4) src = ctr_w;
        else if (oc < 8)  src = dim_w + (oc - 5) * 2304;
        else if (oc == 8) src = ori_w;
        else if (oc < 25) src = kp_w + (oc - 9) * 2304;
        else              src = depth_w;
        g_regw[idx] = src[r];
    }
    if (idx < 26) {
        float b;
        if (idx < 4)       b = bbox_b[idx];
        else if (idx == 4) b = ctr_b[0];
        else if (idx < 8)  b = dim_b[idx - 5];
        else if (idx == 8) b = ori_b[0];
        else if (idx < 25) b = kp_b[idx - 9];
        else               b = depth_b[0];
        g_regb[idx] = b;
    }
}

// ---------------------------------------------------------------------------
// Path+level-batched fp16 implicit-GEMM conv. Tile M=128 x N=128,
// 4 warps of 64x64 each (2M x 2N), 128 threads.
// kind 0: towers, grid (NTILES,4): by>>1 = path, by&1 = oc half.
// kind 1: heads,  grid (NTILES,2): by = path. Writes d_out directly.
// ---------------------------------------------------------------------------
__global__ __launch_bounds__(128, 2) void gemm16(
    const __half* __restrict__ x0, const __half* __restrict__ x1,
    const __half* __restrict__ wt0, const __half* __restrict__ wt1,
    const float* __restrict__ b0p, const float* __restrict__ b1p,
    float* __restrict__ out0, float* __restrict__ out1, int NST, int kind) {
    extern __shared__ __align__(16) uint32_t dynsm[];
    __shared__ int syy[128], sxx[128], sn[128];

    int tid = threadIdx.x;
    int bx = blockIdx.x, by = blockIdx.y;
    int lvl = (bx >= c_tb[1]) + (bx >= c_tb[2]) + (bx >= c_tb[3]) + (bx >= c_tb[4]);
    int H = c_Hs[lvl], W = c_Ws[lvl], HW = c_HWs[lvl], P = c_Ps[lvl];
    int p0 = (bx - c_tb[lvl]) * 128;

    int path, oc0, OC;
    if (kind == 0) {
        path = by >> 1;
        oc0 = (by & 1) * 128;
        OC = 256;
    } else {
        path = by;
        oc0 = 0;
        OC = by ? 26 : 80;
    }
    const __half* x = (path ? x1 : x0) + c_ao[lvl];
    const __half* wt = path ? wt1 : wt0;
    const float* bias = path ? b1p : b0p;
    float* outp = path ? out1 : out0;

    {
        int p = p0 + tid;
        if (p < P) {
            int n = p >= HW ? 1 : 0;
            int rr = p - n * HW;
            int yy = rr / W;
            syy[tid] = yy;
            sxx[tid] = rr - yy * W;
            sn[tid] = n;
        } else {
            syy[tid] = -100000;
            sxx[tid] = -100000;
            sn[tid] = 0;
        }
    }
    __syncthreads();

    int warp = tid >> 5, lane = tid & 31, g = lane >> 2, t4 = lane & 3;
    int mwarp = (warp >> 1) * 64, nwarp = (warp & 1) * 64;

    float acc[4][8][4];
#pragma unroll
    for (int i = 0; i < 4; i++)
#pragma unroll
        for (int j = 0; j < 8; j++)
#pragma unroll
            for (int q = 0; q < 4; q++) acc[i][j][q] = 0.f;

    uint32_t smbase = (uint32_t)__cvta_generic_to_shared(dynsm);

    // ldmatrix lane addressing (within a slot)
    int laneA_row = lane & 15;
    int colA = (lane >> 4) * 4;
    int laneB_row = ((lane >> 4) << 3) + (lane & 7);
    int colB = ((lane >> 3) & 1) * 4;
    uint32_t aAoff = ((mwarp + laneA_row) * PAD + colA) * 4;
    uint32_t aBoff = 10240 + ((nwarp + laneB_row) * PAD + colB) * 4;

    auto load_chunk = [&](int c, int slot) {
        int cc = c, part = 0;
        if (kind) { cc = c % 72; part = c / 72; }
        int tap = cc >> 3;
        int icc = (cc & 7) << 5;
        int ty = tap / 3;
        int dy = ty - 1, dx = tap - ty * 3 - 1;
        uint32_t base = smbase + slot * STAGE_BYTES;
        // A: one row per thread (128 rows), 4 x 16B chunks
        {
            int m = tid;
            int gy = syy[m] + dy, gx = sxx[m] + dx;
            bool v = ((unsigned)gy < (unsigned)H) && ((unsigned)gx < (unsigned)W);
            const __half* src =
                x + ((size_t)(sn[m] * HW + gy * W + gx) * 256 + icc);
            int sz = v ? 16 : 0;
#pragma unroll
            for (int j = 0; j < 4; j++)
                cpa16p(base + (m * PAD + j * 4) * 4,
                       v ? (src + j * 8) : (const __half*)x, sz);
        }
        // B: one row per thread (128 rows), 4 x 16B chunks
        {
            int r = tid;
            const __half* wbase =
                kind ? wt + ((size_t)((part * 9 + tap) * 128)) * 256
                     : wt + ((size_t)(tap * 256 + oc0)) * 256;
            const __half* src = wbase + (size_t)r * 256 + icc;
#pragma unroll
            for (int j = 0; j < 4; j++)
                cpa16p(base + 10240 + (r * PAD + j * 4) * 4, src + j * 8, 16);
        }
        asm volatile("cp.async.commit_group;");
    };

    load_chunk(0, 0);
    load_chunk(1, 1);
    load_chunk(2, 2);

    for (int s = 0; s < NST; s++) {
        int slot = s & 3;
        if (s + 2 < NST) {
            asm volatile("cp.async.wait_group 2;");
        } else if (s + 1 < NST) {
            asm volatile("cp.async.wait_group 1;");
        } else {
            asm volatile("cp.async.wait_group 0;");
        }
        __syncthreads();
        if (s + 3 < NST) load_chunk(s + 3, (s + 3) & 3);

        uint32_t sb = smbase + slot * STAGE_BYTES;
        uint32_t aA = sb + aAoff;
        uint32_t aB = sb + aBoff;
#pragma unroll
        for (int kb = 0; kb < 2; kb++) {
            uint32_t kwb = kb * 8 * 4;
            uint32_t A[4][4], Bv[4][4];
#pragma unroll
            for (int mt = 0; mt < 4; mt++)
                LDSM4(A[mt][0], A[mt][1], A[mt][2], A[mt][3],
                      aA + mt * (16 * PAD * 4) + kwb);
#pragma unroll
            for (int ntp = 0; ntp < 4; ntp++)
                LDSM4(Bv[ntp][0], Bv[ntp][1], Bv[ntp][2], Bv[ntp][3],
                      aB + ntp * (16 * PAD * 4) + kwb);
#pragma unroll
            for (int mt = 0; mt < 4; mt++)
#pragma unroll
                for (int nt = 0; nt < 8; nt++) {
                    int ntp = nt >> 1, j = nt & 1;
                    asm volatile(
                        "mma.sync.aligned.m16n8k16.row.col.f32.f16.f16.f32 "
                        "{%0,%1,%2,%3}, {%4,%5,%6,%7}, {%8,%9}, {%0,%1,%2,%3};"
                        : "+f"(acc[mt][nt][0]), "+f"(acc[mt][nt][1]),
                          "+f"(acc[mt][nt][2]), "+f"(acc[mt][nt][3])
                        : "r"(A[mt][0]), "r"(A[mt][1]), "r"(A[mt][2]), "r"(A[mt][3]),
                          "r"(Bv[ntp][j * 2]), "r"(Bv[ntp][j * 2 + 1]));
                }
        }
    }

    // epilogue
#pragma unroll
    for (int nt = 0; nt < 8; nt++) {
        int oc = oc0 + nwarp + nt * 8 + 2 * t4;
#pragma unroll
        for (int mt = 0; mt < 4; mt++) {
#pragma unroll
            for (int hf = 0; hf < 2; hf++) {
                int r = mwarp + mt * 16 + g + hf * 8;
                if (p0 + r >= P) continue;
                float v0 = acc[mt][nt][hf * 2];
                float v1 = acc[mt][nt][hf * 2 + 1];
                if (kind == 0) {
                    size_t ob = (size_t)c_ao[lvl] + (size_t)(p0 + r) * 256 + oc;
                    float2 st = {v0 + __ldg(&bias[oc]), v1 + __ldg(&bias[oc + 1])};
                    *(float2*)&outp[ob] = st;
                } else if (oc < OC) {
                    long long unit =
                        (long long)sn[r] * TP + c_lb[lvl] + syy[r] * W + sxx[r];
                    v0 += __ldg(&bias[oc]);
                    bool two = (oc + 1) < OC;
                    if (two) v1 += __ldg(&bias[oc + 1]);
                    if (path == 0) {
                        outp[unit * 80 + oc] = v0;
                        if (two) outp[unit * 80 + oc + 1] = v1;
                    } else {
                        if (c_relu[oc]) v0 = fmaxf(v0, 0.f);
                        outp[c_base[oc] + unit * c_ctot[oc] + c_ch[oc]] = v0;
                        if (two) {
                            if (c_relu[oc + 1]) v1 = fmaxf(v1, 0.f);
                            outp[c_base[oc + 1] + unit * c_ctot[oc + 1] +
                                 c_ch[oc + 1]] = v1;
                        }
                    }
                }
            }
        }
    }
}

// ---------------------------------------------------------------------------
// GroupNorm, both paths per launch.
// ---------------------------------------------------------------------------
__global__ void gn_reduce(const float* __restrict__ y0, const float* __restrict__ y1) {
    int bid = blockIdx.x;
    int pathv = bid >= 320 ? 1 : 0;
    int b2 = bid - pathv * 320;
    int l = b2 >> 6;
    int ng = b2 & 63;
    int n = ng >> 5, gr = ng & 31;
    int HW = c_HWs[l];
    const float* y = pathv ? y1 : y0;
    const float* base =
        y + c_ao[l] + (size_t)n * HW * 256 + gr * 8 + (threadIdx.x & 1) * 4;
    int tid = threadIdx.x;
    float s = 0.f, sq = 0.f;
    for (int p = tid >> 1; p < HW; p += 128) {
        float4 v = *(const float4*)&base[(size_t)p * 256];
        s += v.x + v.y + v.z + v.w;
        sq += v.x * v.x + v.y * v.y + v.z * v.z + v.w * v.w;
    }
    __shared__ float ss[256], ssq[256];
    ss[tid] = s; ssq[tid] = sq;
    __syncthreads();
    for (int off = 128; off > 0; off >>= 1) {
        if (tid < off) { ss[tid] += ss[tid + off]; ssq[tid] += ssq[tid + off]; }
        __syncthreads();
    }
    if (tid == 0) {
        float M = 8.f * HW;
        float mu = ss[0] / M;
        float var = ssq[0] / M - mu * mu;
        g_mean[bid] = mu;
        g_inv[bid] = rsqrtf(var + 1e-5f);
    }
}

__global__ void gn_apply(const float* __restrict__ y0, const float* __restrict__ y1,
                         __half* __restrict__ d0, __half* __restrict__ d1,
                         const float* __restrict__ gm0, const float* __restrict__ gm1,
                         const float* __restrict__ bt0, const float* __restrict__ bt1) {
    int idx = blockIdx.x * blockDim.x + threadIdx.x;
    if (idx >= TOTE / 4) return;
    int pathv = blockIdx.y;
    const float* y = pathv ? y1 : y0;
    __half* act = pathv ? d1 : d0;
    const float* gamma = pathv ? gm1 : gm0;
    const float* beta = pathv ? bt1 : bt0;
    int e = idx * 4;
    int l = (e >= c_ao[1]) + (e >= c_ao[2]) + (e >= c_ao[3]) + (e >= c_ao[4]);
    int c = e & 255;
    int pl = (e - c_ao[l]) >> 8;
    int n = pl >= c_HWs[l] ? 1 : 0;
    int ng = pathv * 320 + l * 64 + n * 32 + (c >> 3);
    float mu = g_mean[ng], iv = g_inv[ng];
    float4 v = *(const float4*)&y[e];
    float4 gmv = *(const float4*)&gamma[c];
    float4 btv = *(const float4*)&beta[c];
    __half2 h0 = __floats2half2_rn(fmaxf((v.x - mu) * iv * gmv.x + btv.x, 0.f),
                                   fmaxf((v.y - mu) * iv * gmv.y + btv.y, 0.f));
    __half2 h1 = __floats2half2_rn(fmaxf((v.z - mu) * iv * gmv.z + btv.z, 0.f),
                                   fmaxf((v.w - mu) * iv * gmv.w + btv.w, 0.f));
    uint2 st = {*(uint32_t*)&h0, *(uint32_t*)&h1};
    *(uint2*)&act[e] = st;
}

// ---------------------------------------------------------------------------
// Host orchestration
// ---------------------------------------------------------------------------
extern "C" void kernel_launch(void* const* d_in, const int* in_sizes, int n_in,
                              void* d_out, int out_size) {
    const float* feats[5];
    for (int i = 0; i < 5; i++) feats[i] = (const float*)d_in[i];
    const float* cls_conv_w = (const float*)d_in[5];
    const float* cls_conv_b = (const float*)d_in[6];
    const float* cls_gn_w = (const float*)d_in[7];
    const float* cls_gn_b = (const float*)d_in[8];
    const float* cls_out_w = (const float*)d_in[9];
    const float* cls_out_b = (const float*)d_in[10];
    const float* reg_conv_w = (const float*)d_in[11];
    const float* reg_conv_b = (const float*)d_in[12];
    const float* reg_gn_w = (const float*)d_in[13];
    const float* reg_gn_b = (const float*)d_in[14];
    float* out = (float*)d_out;

    __half *xh, *actA, *actB, *actC, *actD, *wtc, *wtr, *wtco, *wtro;
    float *ybuf, *ybuf2, *regw, *regb;
    cudaGetSymbolAddress((void**)&xh, g_xh);
    cudaGetSymbolAddress((void**)&actA, g_actA);
    cudaGetSymbolAddress((void**)&actB, g_actB);
    cudaGetSymbolAddress((void**)&actC, g_actC);
    cudaGetSymbolAddress((void**)&actD, g_actD);
    cudaGetSymbolAddress((void**)&ybuf, g_y);
    cudaGetSymbolAddress((void**)&ybuf2, g_y2);
    cudaGetSymbolAddress((void**)&regw, g_regw);
    cudaGetSymbolAddress((void**)&regb, g_regb);
    cudaGetSymbolAddress((void**)&wtc, g_wt_cls);
    cudaGetSymbolAddress((void**)&wtr, g_wt_reg);
    cudaGetSymbolAddress((void**)&wtco, g_wtc_out);
    cudaGetSymbolAddress((void**)&wtro, g_wtr_out);

    cudaFuncSetAttribute(gemm16, cudaFuncAttributeMaxDynamicSharedMemorySize,
                         DYN_SMEM);

    pack_reg<<<(26 * 2304 + 255) / 256, 256>>>(
        (const float*)d_in[15], (const float*)d_in[16],
        (const float*)d_in[17], (const float*)d_in[18],
        (const float*)d_in[19], (const float*)d_in[20],
        (const float*)d_in[21], (const float*)d_in[22],
        (const float*)d_in[23], (const float*)d_in[24],
        (const float*)d_in[25], (const float*)d_in[26]);

    int wtN = 4 * 9 * 256 * 256;
    pack_wt<<<(wtN + 255) / 256, 256>>>(cls_conv_w, wtc);
    pack_wt<<<(wtN + 255) / 256, 256>>>(reg_conv_w, wtr);
    int hN = 2 * 9 * 128 * 256;
    pack_headw<<<(hN + 255) / 256, 256>>>(cls_out_w, wtco, 80);
    pack_headw<<<(hN + 255) / 256, 256>>>(regw, wtro, 26);

    to_nhwc_half<<<dim3(475, 8, 10), dim3(32, 32)>>>(feats[0], feats[1], feats[2],
                                                     feats[3], feats[4], xh);

    int gApplyX = (TOTE / 4 + 255) / 256;
    const __half* curc = xh;
    const __half* curr = xh;
    __half* cd[4] = {actA, actB, actA, actB};
    __half* rd[4] = {actC, actD, actC, actD};
    for (int s = 0; s < 4; s++) {
        gemm16<<<dim3(NTILES, 4), 128, DYN_SMEM>>>(
            curc, curr, wtc + (size_t)s * 589824, wtr + (size_t)s * 589824,
            cls_conv_b + s * 256, reg_conv_b + s * 256, ybuf, ybuf2, 72, 0);
        gn_reduce<<<640, 256>>>(ybuf, ybuf2);
        gn_apply<<<dim3(gApplyX, 2), 256>>>(ybuf, ybuf2, cd[s], rd[s],
                                            cls_gn_w + s * 256, reg_gn_w + s * 256,
                                            cls_gn_b + s * 256, reg_gn_b + s * 256);
        curc = cd[s];
        curr = rd[s];
    }
    // heads: by 0 = cls (reads actB), by 1 = reg (reads actD)
    gemm16<<<dim3(NTILES, 2), 128, DYN_SMEM>>>(actB, actD, wtco, wtro, cls_out_b,
                                               regb, out, out, 144, 1);
    (void)in_sizes; (void)n_in; (void)out_size;
}

// round 10
// speedup vs baseline: 1.5620x; 1.5620x over previous
#include <cuda_runtime.h>
#include <cuda_fp16.h>
#include <cstdint>

// ---------------------------------------------------------------------------
// FCOS head, fp16 mma.sync (m16n8k16, fp32 accum). Level+path batched,
// 4-deep cp.async ring (R6 config: 256 thr, warp tile 64x32).
// R9: GroupNorm statistics fused into the tower-GEMM epilogue
// (warp-reduced partial sums + atomicAdd into per-stage buffers).
// ---------------------------------------------------------------------------

#define TP 20267
#define TOTE 10376704          // total NHWC elements (all levels, both batch)
#define PAD 20                 // smem row pitch in uint32 words
#define NTILES 319             // total M-tiles over all levels
#define STAGE_BYTES 20480      // per pipeline slot: A(10240) + B(10240)
#define DYN_SMEM (4 * STAGE_BYTES)

__device__ __half g_xh[TOTE];
__device__ __half g_actA[TOTE];   // cls ping
__device__ __half g_actB[TOTE];   // cls pong
__device__ __half g_actC[TOTE];   // reg ping
__device__ __half g_actD[TOTE];   // reg pong
__device__ float  g_y[TOTE];      // cls conv out
__device__ float  g_y2[TOTE];     // reg conv out
__device__ float  g_gnsum[4 * 640];
__device__ float  g_gnsq[4 * 640];
__device__ float  g_regw[26 * 256 * 9];
__device__ float  g_regb[26];
__device__ __half g_wt_cls[4 * 9 * 256 * 256];   // [s][tap][oc][ic]
__device__ __half g_wt_reg[4 * 9 * 256 * 256];
__device__ __half g_wtc_out[2 * 9 * 128 * 256];  // [part][tap][ocpad][ic]
__device__ __half g_wtr_out[2 * 9 * 128 * 256];

__constant__ int c_Hs[5] = {100, 50, 25, 13, 7};
__constant__ int c_Ws[5] = {152, 76, 38, 19, 10};
__constant__ int c_HWs[5] = {15200, 3800, 950, 247, 70};
__constant__ int c_Ps[5] = {30400, 7600, 1900, 494, 140};
__constant__ int c_tb[5] = {0, 238, 298, 313, 317};
__constant__ int c_ao[5] = {0, 7782400, 9728000, 10214400, 10340864};
__constant__ int c_lb[5] = {0, 15200, 19000, 19950, 20197};

__constant__ long long c_base[26] = {
    3242720LL, 3242720LL, 3242720LL, 3242720LL,
    3404856LL,
    3445390LL, 3445390LL, 3445390LL,
    3566992LL,
    3607526LL, 3607526LL, 3607526LL, 3607526LL, 3607526LL, 3607526LL,
    3607526LL, 3607526LL, 3607526LL, 3607526LL, 3607526LL, 3607526LL,
    3607526LL, 3607526LL, 3607526LL, 3607526LL,
    4256070LL};
__constant__ int c_ctot[26] = {4, 4, 4, 4, 1, 3, 3, 3, 1,
                               16, 16, 16, 16, 16, 16, 16, 16,
                               16, 16, 16, 16, 16, 16, 16, 16, 1};
__constant__ int c_ch[26] = {0, 1, 2, 3, 0, 0, 1, 2, 0,
                             0, 1, 2, 3, 4, 5, 6, 7,
                             8, 9, 10, 11, 12, 13, 14, 15, 0};
__constant__ int c_relu[26] = {1, 1, 1, 1, 0, 0, 0, 0, 0,
                               0, 0, 0, 0, 0, 0, 0, 0,
                               0, 0, 0, 0, 0, 0, 0, 0, 0};

__device__ __forceinline__ void cpa16p(uint32_t d, const void* s, int sz) {
    asm volatile("cp.async.cg.shared.global [%0], [%1], 16, %2;" ::"r"(d), "l"(s), "r"(sz));
}
#define LDSM4(r0, r1, r2, r3, a)                                           \
    asm volatile("ldmatrix.sync.aligned.m8n8.x4.shared.b16 {%0,%1,%2,%3}, [%4];" \
                 : "=r"(r0), "=r"(r1), "=r"(r2), "=r"(r3) : "r"(a))

__global__ void zero_stats() {
    int i = blockIdx.x * blockDim.x + threadIdx.x;
    if (i < 4 * 640) { g_gnsum[i] = 0.f; g_gnsq[i] = 0.f; }
}

// ---------------------------------------------------------------------------
// NCHW fp32 -> NHWC half, all levels in one launch. grid (475, 8, 10)
// ---------------------------------------------------------------------------
__global__ void to_nhwc_half(const float* __restrict__ f0, const float* __restrict__ f1,
                             const float* __restrict__ f2, const float* __restrict__ f3,
                             const float* __restrict__ f4, __half* __restrict__ xh) {
    __shared__ float t[32][33];
    int z = blockIdx.z;
    int lvl = z >> 1, n = z & 1;
    int HW = c_HWs[lvl];
    int p0 = blockIdx.x * 32;
    if (p0 >= HW) return;
    const float* src = lvl == 0 ? f0 : lvl == 1 ? f1 : lvl == 2 ? f2 : lvl == 3 ? f3 : f4;
    __half* dst = xh + c_ao[lvl];
    int c0 = blockIdx.y * 32;
    int tx = threadIdx.x, ty = threadIdx.y;
    int p = p0 + tx;
    if (p < HW) t[ty][tx] = src[((size_t)(n * 256 + c0 + ty)) * HW + p];
    __syncthreads();
    int p2 = p0 + ty, c2 = c0 + tx;
    if (p2 < HW) dst[((size_t)(n * HW + p2)) * 256 + c2] = __float2half_rn(t[tx][ty]);
}

// ---------------------------------------------------------------------------
// Weight packs
// ---------------------------------------------------------------------------
__global__ void pack_wt(const float* __restrict__ w, __half* __restrict__ wt) {
    int idx = blockIdx.x * blockDim.x + threadIdx.x;
    if (idx >= 4 * 9 * 256 * 256) return;
    int ic = idx & 255;
    int oc = (idx >> 8) & 255;
    int tap = (idx >> 16) % 9;
    int s = idx / 589824;
    wt[idx] = __float2half_rn(w[(((size_t)(s * 256 + oc) * 256 + ic) * 9) + tap]);
}

__global__ void pack_headw(const float* __restrict__ src, __half* __restrict__ dst,
                           int OC) {
    int idx = blockIdx.x * blockDim.x + threadIdx.x;
    if (idx >= 2 * 9 * 128 * 256) return;
    int ic = idx & 255;
    int oc = (idx >> 8) & 127;
    int tap = (idx >> 15) % 9;
    int part = idx / (9 * 128 * 256);
    float v = 0.f;
    if (oc < OC) v = src[((size_t)oc * 256 + ic) * 9 + tap];
    __half hi = __float2half_rn(v);
    dst[idx] = (part == 0) ? hi : __float2half_rn(v - __half2float(hi));
}

__global__ void pack_reg(const float* __restrict__ bbox_w, const float* __restrict__ bbox_b,
                         const float* __restrict__ ctr_w,  const float* __restrict__ ctr_b,
                         const float* __restrict__ dim_w,  const float* __restrict__ dim_b,
                         const float* __restrict__ ori_w,  const float* __restrict__ ori_b,
                         const float* __restrict__ kp_w,   const float* __restrict__ kp_b,
                         const float* __restrict__ depth_w,const float* __restrict__ depth_b) {
    int idx = blockIdx.x * blockDim.x + threadIdx.x;
    int total = 26 * 2304;
    if (idx < total) {
        int oc = idx / 2304;
        int r = idx % 2304;
        const float* src;
        if (oc < 4)       src = bbox_w + oc * 2304;
        else if (oc == 4) src = ctr_w;
        else if (oc < 8)  src = dim_w + (oc - 5) * 2304;
        else if (oc == 8) src = ori_w;
        else if (oc < 25) src = kp_w + (oc - 9) * 2304;
        else              src = depth_w;
        g_regw[idx] = src[r];
    }
    if (idx < 26) {
        float b;
        if (idx < 4)       b = bbox_b[idx];
        else if (idx == 4) b = ctr_b[0];
        else if (idx < 8)  b = dim_b[idx - 5];
        else if (idx == 8) b = ori_b[0];
        else if (idx < 25) b = kp_b[idx - 9];
        else               b = depth_b[0];
        g_regb[idx] = b;
    }
}

// ---------------------------------------------------------------------------
// Path+level-batched fp16 implicit-GEMM conv. M=128 pos x N=128 oc, 8 warps
// (warp tile 64x32). kind 0: towers, grid (NTILES,4); kind 1: heads,
// grid (NTILES,2). Tower epilogue also emits GN partial sums (gsum/gsq).
// ---------------------------------------------------------------------------
__global__ __launch_bounds__(256, 2) void gemm16(
    const __half* __restrict__ x0, const __half* __restrict__ x1,
    const __half* __restrict__ wt0, const __half* __restrict__ wt1,
    const float* __restrict__ b0p, const float* __restrict__ b1p,
    float* __restrict__ out0, float* __restrict__ out1,
    float* __restrict__ gsum, float* __restrict__ gsq, int NST, int kind) {
    extern __shared__ __align__(16) uint32_t dynsm[];
    __shared__ int syy[128], sxx[128], sn[128];

    int tid = threadIdx.x;
    int bx = blockIdx.x, by = blockIdx.y;
    int lvl = (bx >= c_tb[1]) + (bx >= c_tb[2]) + (bx >= c_tb[3]) + (bx >= c_tb[4]);
    int H = c_Hs[lvl], W = c_Ws[lvl], HW = c_HWs[lvl], P = c_Ps[lvl];
    int p0 = (bx - c_tb[lvl]) * 128;

    int path, oc0, OC;
    if (kind == 0) {
        path = by >> 1;
        oc0 = (by & 1) * 128;
        OC = 256;
    } else {
        path = by;
        oc0 = 0;
        OC = by ? 26 : 80;
    }
    const __half* x = (path ? x1 : x0) + c_ao[lvl];
    const __half* wt = path ? wt1 : wt0;
    const float* bias = path ? b1p : b0p;
    float* outp = path ? out1 : out0;

    if (tid < 128) {
        int p = p0 + tid;
        if (p < P) {
            int n = p >= HW ? 1 : 0;
            int rr = p - n * HW;
            int yy = rr / W;
            syy[tid] = yy;
            sxx[tid] = rr - yy * W;
            sn[tid] = n;
        } else {
            syy[tid] = -100000;
            sxx[tid] = -100000;
            sn[tid] = 0;
        }
    }
    __syncthreads();

    int warp = tid >> 5, lane = tid & 31, g = lane >> 2, t4 = lane & 3;
    int mwarp = (warp >> 2) * 64, nwarp = (warp & 3) * 32;

    float acc[4][4][4];
#pragma unroll
    for (int i = 0; i < 4; i++)
#pragma unroll
        for (int j = 0; j < 4; j++)
#pragma unroll
            for (int q = 0; q < 4; q++) acc[i][j][q] = 0.f;

    int m0 = tid >> 2, cw0 = tid & 3;
    uint32_t smbase = (uint32_t)__cvta_generic_to_shared(dynsm);

    // ldmatrix lane addressing (within a slot)
    int laneA_row = lane & 15;
    int colA = (lane >> 4) * 4;
    int laneB_row = ((lane >> 4) << 3) + (lane & 7);
    int colB = ((lane >> 3) & 1) * 4;
    uint32_t aAoff = ((mwarp + laneA_row) * PAD + colA) * 4;
    uint32_t aBoff = 10240 + ((nwarp + laneB_row) * PAD + colB) * 4;

    auto load_chunk = [&](int c, int slot) {
        int cc = c, part = 0;
        if (kind) { cc = c % 72; part = c / 72; }
        int tap = cc >> 3;
        int icc = (cc & 7) << 5;
        int ty = tap / 3;
        int dy = ty - 1, dx = tap - ty * 3 - 1;
        uint32_t base = smbase + slot * STAGE_BYTES;
#pragma unroll
        for (int j = 0; j < 2; j++) {
            int m = m0 + j * 64;
            int gy = syy[m] + dy, gx = sxx[m] + dx;
            bool v = ((unsigned)gy < (unsigned)H) && ((unsigned)gx < (unsigned)W);
            const __half* src =
                x + ((size_t)(sn[m] * HW + gy * W + gx) * 256 + icc + cw0 * 8);
            cpa16p(base + (m * PAD + cw0 * 4) * 4, v ? src : (const __half*)x,
                   v ? 16 : 0);
        }
        const __half* wbase =
            kind ? wt + ((size_t)((part * 9 + tap) * 128)) * 256
                 : wt + ((size_t)(tap * 256 + oc0)) * 256;
#pragma unroll
        for (int j = 0; j < 2; j++) {
            int ocr = m0 + j * 64;
            cpa16p(base + 10240 + (ocr * PAD + cw0 * 4) * 4,
                   wbase + (size_t)ocr * 256 + icc + cw0 * 8, 16);
        }
        asm volatile("cp.async.commit_group;");
    };

    load_chunk(0, 0);
    load_chunk(1, 1);
    load_chunk(2, 2);

    for (int s = 0; s < NST; s++) {
        int slot = s & 3;
        if (s + 2 < NST) {
            asm volatile("cp.async.wait_group 2;");
        } else if (s + 1 < NST) {
            asm volatile("cp.async.wait_group 1;");
        } else {
            asm volatile("cp.async.wait_group 0;");
        }
        __syncthreads();
        if (s + 3 < NST) load_chunk(s + 3, (s + 3) & 3);

        uint32_t sb = smbase + slot * STAGE_BYTES;
        uint32_t aA = sb + aAoff;
        uint32_t aB = sb + aBoff;
#pragma unroll
        for (int kb = 0; kb < 2; kb++) {
            uint32_t kwb = kb * 8 * 4;
            uint32_t A[4][4], Bv[2][4];
#pragma unroll
            for (int mt = 0; mt < 4; mt++)
                LDSM4(A[mt][0], A[mt][1], A[mt][2], A[mt][3],
                      aA + mt * (16 * PAD * 4) + kwb);
#pragma unroll
            for (int ntp = 0; ntp < 2; ntp++)
                LDSM4(Bv[ntp][0], Bv[ntp][1], Bv[ntp][2], Bv[ntp][3],
                      aB + ntp * (16 * PAD * 4) + kwb);
#pragma unroll
            for (int mt = 0; mt < 4; mt++)
#pragma unroll
                for (int nt = 0; nt < 4; nt++) {
                    int ntp = nt >> 1, j = nt & 1;
                    asm volatile(
                        "mma.sync.aligned.m16n8k16.row.col.f32.f16.f16.f32 "
                        "{%0,%1,%2,%3}, {%4,%5,%6,%7}, {%8,%9}, {%0,%1,%2,%3};"
                        : "+f"(acc[mt][nt][0]), "+f"(acc[mt][nt][1]),
                          "+f"(acc[mt][nt][2]), "+f"(acc[mt][nt][3])
                        : "r"(A[mt][0]), "r"(A[mt][1]), "r"(A[mt][2]), "r"(A[mt][3]),
                          "r"(Bv[ntp][j * 2]), "r"(Bv[ntp][j * 2 + 1]));
                }
        }
    }

    // epilogue
#pragma unroll
    for (int nt = 0; nt < 4; nt++) {
        int oc = oc0 + nwarp + nt * 8 + 2 * t4;
        float s0 = 0.f, q0 = 0.f, s1 = 0.f, q1 = 0.f;
#pragma unroll
        for (int mt = 0; mt < 4; mt++) {
#pragma unroll
            for (int hf = 0; hf < 2; hf++) {
                int r = mwarp + mt * 16 + g + hf * 8;
                if (p0 + r >= P) continue;
                float v0 = acc[mt][nt][hf * 2];
                float v1 = acc[mt][nt][hf * 2 + 1];
                if (kind == 0) {
                    v0 += __ldg(&bias[oc]);
                    v1 += __ldg(&bias[oc + 1]);
                    size_t ob = (size_t)c_ao[lvl] + (size_t)(p0 + r) * 256 + oc;
                    float2 st = {v0, v1};
                    *(float2*)&outp[ob] = st;
                    if (sn[r]) { s1 += v0 + v1; q1 += v0 * v0 + v1 * v1; }
                    else       { s0 += v0 + v1; q0 += v0 * v0 + v1 * v1; }
                } else if (oc < OC) {
                    long long unit =
                        (long long)sn[r] * TP + c_lb[lvl] + syy[r] * W + sxx[r];
                    v0 += __ldg(&bias[oc]);
                    v1 += __ldg(&bias[oc + 1]);
                    if (path == 0) {
                        outp[unit * 80 + oc] = v0;
                        outp[unit * 80 + oc + 1] = v1;
                    } else {
                        if (c_relu[oc]) v0 = fmaxf(v0, 0.f);
                        if (c_relu[oc + 1]) v1 = fmaxf(v1, 0.f);
                        outp[c_base[oc] + unit * c_ctot[oc] + c_ch[oc]] = v0;
                        outp[c_base[oc + 1] + unit * c_ctot[oc + 1] + c_ch[oc + 1]] = v1;
                    }
                }
            }
        }
        if (kind == 0) {
#pragma unroll
            for (int o = 16; o > 0; o >>= 1) {
                s0 += __shfl_xor_sync(0xffffffffu, s0, o);
                q0 += __shfl_xor_sync(0xffffffffu, q0, o);
                s1 += __shfl_xor_sync(0xffffffffu, s1, o);
                q1 += __shfl_xor_sync(0xffffffffu, q1, o);
            }
            if (lane == 0) {
                int gb = path * 320 + lvl * 64 + ((oc0 + nwarp + nt * 8) >> 3);
                atomicAdd(&gsum[gb], s0);
                atomicAdd(&gsq[gb], q0);
                if (s1 != 0.f || q1 != 0.f) {
                    atomicAdd(&gsum[gb + 32], s1);
                    atomicAdd(&gsq[gb + 32], q1);
                }
            }
        }
    }
}

// ---------------------------------------------------------------------------
// GroupNorm apply: computes mu/inv from fused-epilogue sums.
// ---------------------------------------------------------------------------
__global__ void gn_apply(const float* __restrict__ y0, const float* __restrict__ y1,
                         __half* __restrict__ d0, __half* __restrict__ d1,
                         const float* __restrict__ gm0, const float* __restrict__ gm1,
                         const float* __restrict__ bt0, const float* __restrict__ bt1,
                         const float* __restrict__ gsum, const float* __restrict__ gsq) {
    int idx = blockIdx.x * blockDim.x + threadIdx.x;
    if (idx >= TOTE / 4) return;
    int pathv = blockIdx.y;
    const float* y = pathv ? y1 : y0;
    __half* act = pathv ? d1 : d0;
    const float* gamma = pathv ? gm1 : gm0;
    const float* beta = pathv ? bt1 : bt0;
    int e = idx * 4;
    int l = (e >= c_ao[1]) + (e >= c_ao[2]) + (e >= c_ao[3]) + (e >= c_ao[4]);
    int c = e & 255;
    int pl = (e - c_ao[l]) >> 8;
    int n = pl >= c_HWs[l] ? 1 : 0;
    int ng = pathv * 320 + l * 64 + n * 32 + (c >> 3);
    float M = 8.f * c_HWs[l];
    float sm = gsum[ng];
    float mu = sm / M;
    float iv = rsqrtf(gsq[ng] / M - mu * mu + 1e-5f);
    float4 v = *(const float4*)&y[e];
    float4 gmv = *(const float4*)&gamma[c];
    float4 btv = *(const float4*)&beta[c];
    __half2 h0 = __floats2half2_rn(fmaxf((v.x - mu) * iv * gmv.x + btv.x, 0.f),
                                   fmaxf((v.y - mu) * iv * gmv.y + btv.y, 0.f));
    __half2 h1 = __floats2half2_rn(fmaxf((v.z - mu) * iv * gmv.z + btv.z, 0.f),
                                   fmaxf((v.w - mu) * iv * gmv.w + btv.w, 0.f));
    uint2 st = {*(uint32_t*)&h0, *(uint32_t*)&h1};
    *(uint2*)&act[e] = st;
}

// ---------------------------------------------------------------------------
// Host orchestration
// ---------------------------------------------------------------------------
extern "C" void kernel_launch(void* const* d_in, const int* in_sizes, int n_in,
                              void* d_out, int out_size) {
    const float* feats[5];
    for (int i = 0; i < 5; i++) feats[i] = (const float*)d_in[i];
    const float* cls_conv_w = (const float*)d_in[5];
    const float* cls_conv_b = (const float*)d_in[6];
    const float* cls_gn_w = (const float*)d_in[7];
    const float* cls_gn_b = (const float*)d_in[8];
    const float* cls_out_w = (const float*)d_in[9];
    const float* cls_out_b = (const float*)d_in[10];
    const float* reg_conv_w = (const float*)d_in[11];
    const float* reg_conv_b = (const float*)d_in[12];
    const float* reg_gn_w = (const float*)d_in[13];
    const float* reg_gn_b = (const float*)d_in[14];
    float* out = (float*)d_out;

    __half *xh, *actA, *actB, *actC, *actD, *wtc, *wtr, *wtco, *wtro;
    float *ybuf, *ybuf2, *regw, *regb, *gsum, *gsq;
    cudaGetSymbolAddress((void**)&xh, g_xh);
    cudaGetSymbolAddress((void**)&actA, g_actA);
    cudaGetSymbolAddress((void**)&actB, g_actB);
    cudaGetSymbolAddress((void**)&actC, g_actC);
    cudaGetSymbolAddress((void**)&actD, g_actD);
    cudaGetSymbolAddress((void**)&ybuf, g_y);
    cudaGetSymbolAddress((void**)&ybuf2, g_y2);
    cudaGetSymbolAddress((void**)&regw, g_regw);
    cudaGetSymbolAddress((void**)&regb, g_regb);
    cudaGetSymbolAddress((void**)&wtc, g_wt_cls);
    cudaGetSymbolAddress((void**)&wtr, g_wt_reg);
    cudaGetSymbolAddress((void**)&wtco, g_wtc_out);
    cudaGetSymbolAddress((void**)&wtro, g_wtr_out);
    cudaGetSymbolAddress((void**)&gsum, g_gnsum);
    cudaGetSymbolAddress((void**)&gsq, g_gnsq);

    cudaFuncSetAttribute(gemm16, cudaFuncAttributeMaxDynamicSharedMemorySize,
                         DYN_SMEM);

    zero_stats<<<10, 256>>>();

    pack_reg<<<(26 * 2304 + 255) / 256, 256>>>(
        (const float*)d_in[15], (const float*)d_in[16],
        (const float*)d_in[17], (const float*)d_in[18],
        (const float*)d_in[19], (const float*)d_in[20],
        (const float*)d_in[21], (const float*)d_in[22],
        (const float*)d_in[23], (const float*)d_in[24],
        (const float*)d_in[25], (const float*)d_in[26]);

    int wtN = 4 * 9 * 256 * 256;
    pack_wt<<<(wtN + 255) / 256, 256>>>(cls_conv_w, wtc);
    pack_wt<<<(wtN + 255) / 256, 256>>>(reg_conv_w, wtr);
    int hN = 2 * 9 * 128 * 256;
    pack_headw<<<(hN + 255) / 256, 256>>>(cls_out_w, wtco, 80);
    pack_headw<<<(hN + 255) / 256, 256>>>(regw, wtro, 26);

    to_nhwc_half<<<dim3(475, 8, 10), dim3(32, 32)>>>(feats[0], feats[1], feats[2],
                                                     feats[3], feats[4], xh);

    int gApplyX = (TOTE / 4 + 255) / 256;
    const __half* curc = xh;
    const __half* curr = xh;
    __half* cd[4] = {actA, actB, actA, actB};
    __half* rd[4] = {actC, actD, actC, actD};
    for (int s = 0; s < 4; s++) {
        gemm16<<<dim3(NTILES, 4), 256, DYN_SMEM>>>(
            curc, curr, wtc + (size_t)s * 589824, wtr + (size_t)s * 589824,
            cls_conv_b + s * 256, reg_conv_b + s * 256, ybuf, ybuf2,
            gsum + s * 640, gsq + s * 640, 72, 0);
        gn_apply<<<dim3(gApplyX, 2), 256>>>(ybuf, ybuf2, cd[s], rd[s],
                                            cls_gn_w + s * 256, reg_gn_w + s * 256,
                                            cls_gn_b + s * 256, reg_gn_b + s * 256,
                                            gsum + s * 640, gsq + s * 640);
        curc = cd[s];
        curr = rd[s];
    }
    // heads: by 0 = cls (reads actB), by 1 = reg (reads actD)
    gemm16<<<dim3(NTILES, 2), 256, DYN_SMEM>>>(actB, actD, wtco, wtro, cls_out_b,
                                               regb, out, out, nullptr, nullptr,
                                               144, 1);
    (void)in_sizes; (void)n_in; (void)out_size;
}

// round 11
// speedup vs baseline: 1.7469x; 1.1184x over previous
#include <cuda_runtime.h>
#include <cuda_fp16.h>
#include <cstdint>

// ---------------------------------------------------------------------------
// FCOS head, fp16 mma.sync (m16n8k16, fp32 accum). Level+path batched,
// 4-deep cp.async ring (R6 config: 256 thr, warp tile 64x32).
// R9: GN stats fused into tower epilogue. R10: heads single fp16 pass
// (hi/lo split removed; NST 144 -> 72).
// ---------------------------------------------------------------------------

#define TP 20267
#define TOTE 10376704          // total NHWC elements (all levels, both batch)
#define PAD 20                 // smem row pitch in uint32 words
#define NTILES 319             // total M-tiles over all levels
#define STAGE_BYTES 20480      // per pipeline slot: A(10240) + B(10240)
#define DYN_SMEM (4 * STAGE_BYTES)

__device__ __half g_xh[TOTE];
__device__ __half g_actA[TOTE];   // cls ping
__device__ __half g_actB[TOTE];   // cls pong
__device__ __half g_actC[TOTE];   // reg ping
__device__ __half g_actD[TOTE];   // reg pong
__device__ float  g_y[TOTE];      // cls conv out
__device__ float  g_y2[TOTE];     // reg conv out
__device__ float  g_gnsum[4 * 640];
__device__ float  g_gnsq[4 * 640];
__device__ float  g_regw[26 * 256 * 9];
__device__ float  g_regb[26];
__device__ __half g_wt_cls[4 * 9 * 256 * 256];   // [s][tap][oc][ic]
__device__ __half g_wt_reg[4 * 9 * 256 * 256];
__device__ __half g_wtc_out[9 * 128 * 256];      // [tap][ocpad][ic]
__device__ __half g_wtr_out[9 * 128 * 256];

__constant__ int c_Hs[5] = {100, 50, 25, 13, 7};
__constant__ int c_Ws[5] = {152, 76, 38, 19, 10};
__constant__ int c_HWs[5] = {15200, 3800, 950, 247, 70};
__constant__ int c_Ps[5] = {30400, 7600, 1900, 494, 140};
__constant__ int c_tb[5] = {0, 238, 298, 313, 317};
__constant__ int c_ao[5] = {0, 7782400, 9728000, 10214400, 10340864};
__constant__ int c_lb[5] = {0, 15200, 19000, 19950, 20197};

__constant__ long long c_base[26] = {
    3242720LL, 3242720LL, 3242720LL, 3242720LL,
    3404856LL,
    3445390LL, 3445390LL, 3445390LL,
    3566992LL,
    3607526LL, 3607526LL, 3607526LL, 3607526LL, 3607526LL, 3607526LL,
    3607526LL, 3607526LL, 3607526LL, 3607526LL, 3607526LL, 3607526LL,
    3607526LL, 3607526LL, 3607526LL, 3607526LL,
    4256070LL};
__constant__ int c_ctot[26] = {4, 4, 4, 4, 1, 3, 3, 3, 1,
                               16, 16, 16, 16, 16, 16, 16, 16,
                               16, 16, 16, 16, 16, 16, 16, 16, 1};
__constant__ int c_ch[26] = {0, 1, 2, 3, 0, 0, 1, 2, 0,
                             0, 1, 2, 3, 4, 5, 6, 7,
                             8, 9, 10, 11, 12, 13, 14, 15, 0};
__constant__ int c_relu[26] = {1, 1, 1, 1, 0, 0, 0, 0, 0,
                               0, 0, 0, 0, 0, 0, 0, 0,
                               0, 0, 0, 0, 0, 0, 0, 0, 0};

__device__ __forceinline__ void cpa16p(uint32_t d, const void* s, int sz) {
    asm volatile("cp.async.cg.shared.global [%0], [%1], 16, %2;" ::"r"(d), "l"(s), "r"(sz));
}
#define LDSM4(r0, r1, r2, r3, a)                                           \
    asm volatile("ldmatrix.sync.aligned.m8n8.x4.shared.b16 {%0,%1,%2,%3}, [%4];" \
                 : "=r"(r0), "=r"(r1), "=r"(r2), "=r"(r3) : "r"(a))

__global__ void zero_stats() {
    int i = blockIdx.x * blockDim.x + threadIdx.x;
    if (i < 4 * 640) { g_gnsum[i] = 0.f; g_gnsq[i] = 0.f; }
}

// ---------------------------------------------------------------------------
// NCHW fp32 -> NHWC half, all levels in one launch. grid (475, 8, 10)
// ---------------------------------------------------------------------------
__global__ void to_nhwc_half(const float* __restrict__ f0, const float* __restrict__ f1,
                             const float* __restrict__ f2, const float* __restrict__ f3,
                             const float* __restrict__ f4, __half* __restrict__ xh) {
    __shared__ float t[32][33];
    int z = blockIdx.z;
    int lvl = z >> 1, n = z & 1;
    int HW = c_HWs[lvl];
    int p0 = blockIdx.x * 32;
    if (p0 >= HW) return;
    const float* src = lvl == 0 ? f0 : lvl == 1 ? f1 : lvl == 2 ? f2 : lvl == 3 ? f3 : f4;
    __half* dst = xh + c_ao[lvl];
    int c0 = blockIdx.y * 32;
    int tx = threadIdx.x, ty = threadIdx.y;
    int p = p0 + tx;
    if (p < HW) t[ty][tx] = src[((size_t)(n * 256 + c0 + ty)) * HW + p];
    __syncthreads();
    int p2 = p0 + ty, c2 = c0 + tx;
    if (p2 < HW) dst[((size_t)(n * HW + p2)) * 256 + c2] = __float2half_rn(t[tx][ty]);
}

// ---------------------------------------------------------------------------
// Weight packs
// ---------------------------------------------------------------------------
__global__ void pack_wt(const float* __restrict__ w, __half* __restrict__ wt) {
    int idx = blockIdx.x * blockDim.x + threadIdx.x;
    if (idx >= 4 * 9 * 256 * 256) return;
    int ic = idx & 255;
    int oc = (idx >> 8) & 255;
    int tap = (idx >> 16) % 9;
    int s = idx / 589824;
    wt[idx] = __float2half_rn(w[(((size_t)(s * 256 + oc) * 256 + ic) * 9) + tap]);
}

__global__ void pack_headw(const float* __restrict__ src, __half* __restrict__ dst,
                           int OC) {
    int idx = blockIdx.x * blockDim.x + threadIdx.x;
    if (idx >= 9 * 128 * 256) return;
    int ic = idx & 255;
    int oc = (idx >> 8) & 127;
    int tap = idx >> 15;
    float v = 0.f;
    if (oc < OC) v = src[((size_t)oc * 256 + ic) * 9 + tap];
    dst[idx] = __float2half_rn(v);
}

__global__ void pack_reg(const float* __restrict__ bbox_w, const float* __restrict__ bbox_b,
                         const float* __restrict__ ctr_w,  const float* __restrict__ ctr_b,
                         const float* __restrict__ dim_w,  const float* __restrict__ dim_b,
                         const float* __restrict__ ori_w,  const float* __restrict__ ori_b,
                         const float* __restrict__ kp_w,   const float* __restrict__ kp_b,
                         const float* __restrict__ depth_w,const float* __restrict__ depth_b) {
    int idx = blockIdx.x * blockDim.x + threadIdx.x;
    int total = 26 * 2304;
    if (idx < total) {
        int oc = idx / 2304;
        int r = idx % 2304;
        const float* src;
        if (oc < 4)       src = bbox_w + oc * 2304;
        else if (oc == 4) src = ctr_w;
        else if (oc < 8)  src = dim_w + (oc - 5) * 2304;
        else if (oc == 8) src = ori_w;
        else if (oc < 25) src = kp_w + (oc - 9) * 2304;
        else              src = depth_w;
        g_regw[idx] = src[r];
    }
    if (idx < 26) {
        float b;
        if (idx < 4)       b = bbox_b[idx];
        else if (idx == 4) b = ctr_b[0];
        else if (idx < 8)  b = dim_b[idx - 5];
        else if (idx == 8) b = ori_b[0];
        else if (idx < 25) b = kp_b[idx - 9];
        else               b = depth_b[0];
        g_regb[idx] = b;
    }
}

// ---------------------------------------------------------------------------
// Path+level-batched fp16 implicit-GEMM conv. M=128 pos x N=128 oc, 8 warps
// (warp tile 64x32). kind 0: towers, grid (NTILES,4); kind 1: heads,
// grid (NTILES,2). Tower epilogue also emits GN partial sums (gsum/gsq).
// ---------------------------------------------------------------------------
__global__ __launch_bounds__(256, 2) void gemm16(
    const __half* __restrict__ x0, const __half* __restrict__ x1,
    const __half* __restrict__ wt0, const __half* __restrict__ wt1,
    const float* __restrict__ b0p, const float* __restrict__ b1p,
    float* __restrict__ out0, float* __restrict__ out1,
    float* __restrict__ gsum, float* __restrict__ gsq, int NST, int kind) {
    extern __shared__ __align__(16) uint32_t dynsm[];
    __shared__ int syy[128], sxx[128], sn[128];

    int tid = threadIdx.x;
    int bx = blockIdx.x, by = blockIdx.y;
    int lvl = (bx >= c_tb[1]) + (bx >= c_tb[2]) + (bx >= c_tb[3]) + (bx >= c_tb[4]);
    int H = c_Hs[lvl], W = c_Ws[lvl], HW = c_HWs[lvl], P = c_Ps[lvl];
    int p0 = (bx - c_tb[lvl]) * 128;

    int path, oc0, OC;
    if (kind == 0) {
        path = by >> 1;
        oc0 = (by & 1) * 128;
        OC = 256;
    } else {
        path = by;
        oc0 = 0;
        OC = by ? 26 : 80;
    }
    const __half* x = (path ? x1 : x0) + c_ao[lvl];
    const __half* wt = path ? wt1 : wt0;
    const float* bias = path ? b1p : b0p;
    float* outp = path ? out1 : out0;

    if (tid < 128) {
        int p = p0 + tid;
        if (p < P) {
            int n = p >= HW ? 1 : 0;
            int rr = p - n * HW;
            int yy = rr / W;
            syy[tid] = yy;
            sxx[tid] = rr - yy * W;
            sn[tid] = n;
        } else {
            syy[tid] = -100000;
            sxx[tid] = -100000;
            sn[tid] = 0;
        }
    }
    __syncthreads();

    int warp = tid >> 5, lane = tid & 31, g = lane >> 2, t4 = lane & 3;
    int mwarp = (warp >> 2) * 64, nwarp = (warp & 3) * 32;

    float acc[4][4][4];
#pragma unroll
    for (int i = 0; i < 4; i++)
#pragma unroll
        for (int j = 0; j < 4; j++)
#pragma unroll
            for (int q = 0; q < 4; q++) acc[i][j][q] = 0.f;

    int m0 = tid >> 2, cw0 = tid & 3;
    uint32_t smbase = (uint32_t)__cvta_generic_to_shared(dynsm);

    // ldmatrix lane addressing (within a slot)
    int laneA_row = lane & 15;
    int colA = (lane >> 4) * 4;
    int laneB_row = ((lane >> 4) << 3) + (lane & 7);
    int colB = ((lane >> 3) & 1) * 4;
    uint32_t aAoff = ((mwarp + laneA_row) * PAD + colA) * 4;
    uint32_t aBoff = 10240 + ((nwarp + laneB_row) * PAD + colB) * 4;

    auto load_chunk = [&](int c, int slot) {
        int tap = c >> 3;
        int icc = (c & 7) << 5;
        int ty = tap / 3;
        int dy = ty - 1, dx = tap - ty * 3 - 1;
        uint32_t base = smbase + slot * STAGE_BYTES;
#pragma unroll
        for (int j = 0; j < 2; j++) {
            int m = m0 + j * 64;
            int gy = syy[m] + dy, gx = sxx[m] + dx;
            bool v = ((unsigned)gy < (unsigned)H) && ((unsigned)gx < (unsigned)W);
            const __half* src =
                x + ((size_t)(sn[m] * HW + gy * W + gx) * 256 + icc + cw0 * 8);
            cpa16p(base + (m * PAD + cw0 * 4) * 4, v ? src : (const __half*)x,
                   v ? 16 : 0);
        }
        const __half* wbase =
            kind ? wt + ((size_t)(tap * 128)) * 256
                 : wt + ((size_t)(tap * 256 + oc0)) * 256;
#pragma unroll
        for (int j = 0; j < 2; j++) {
            int ocr = m0 + j * 64;
            cpa16p(base + 10240 + (ocr * PAD + cw0 * 4) * 4,
                   wbase + (size_t)ocr * 256 + icc + cw0 * 8, 16);
        }
        asm volatile("cp.async.commit_group;");
    };

    load_chunk(0, 0);
    load_chunk(1, 1);
    load_chunk(2, 2);

    for (int s = 0; s < NST; s++) {
        int slot = s & 3;
        if (s + 2 < NST) {
            asm volatile("cp.async.wait_group 2;");
        } else if (s + 1 < NST) {
            asm volatile("cp.async.wait_group 1;");
        } else {
            asm volatile("cp.async.wait_group 0;");
        }
        __syncthreads();
        if (s + 3 < NST) load_chunk(s + 3, (s + 3) & 3);

        uint32_t sb = smbase + slot * STAGE_BYTES;
        uint32_t aA = sb + aAoff;
        uint32_t aB = sb + aBoff;
#pragma unroll
        for (int kb = 0; kb < 2; kb++) {
            uint32_t kwb = kb * 8 * 4;
            uint32_t A[4][4], Bv[2][4];
#pragma unroll
            for (int mt = 0; mt < 4; mt++)
                LDSM4(A[mt][0], A[mt][1], A[mt][2], A[mt][3],
                      aA + mt * (16 * PAD * 4) + kwb);
#pragma unroll
            for (int ntp = 0; ntp < 2; ntp++)
                LDSM4(Bv[ntp][0], Bv[ntp][1], Bv[ntp][2], Bv[ntp][3],
                      aB + ntp * (16 * PAD * 4) + kwb);
#pragma unroll
            for (int mt = 0; mt < 4; mt++)
#pragma unroll
                for (int nt = 0; nt < 4; nt++) {
                    int ntp = nt >> 1, j = nt & 1;
                    asm volatile(
                        "mma.sync.aligned.m16n8k16.row.col.f32.f16.f16.f32 "
                        "{%0,%1,%2,%3}, {%4,%5,%6,%7}, {%8,%9}, {%0,%1,%2,%3};"
                        : "+f"(acc[mt][nt][0]), "+f"(acc[mt][nt][1]),
                          "+f"(acc[mt][nt][2]), "+f"(acc[mt][nt][3])
                        : "r"(A[mt][0]), "r"(A[mt][1]), "r"(A[mt][2]), "r"(A[mt][3]),
                          "r"(Bv[ntp][j * 2]), "r"(Bv[ntp][j * 2 + 1]));
                }
        }
    }

    // epilogue
#pragma unroll
    for (int nt = 0; nt < 4; nt++) {
        int oc = oc0 + nwarp + nt * 8 + 2 * t4;
        float s0 = 0.f, q0 = 0.f, s1 = 0.f, q1 = 0.f;
#pragma unroll
        for (int mt = 0; mt < 4; mt++) {
#pragma unroll
            for (int hf = 0; hf < 2; hf++) {
                int r = mwarp + mt * 16 + g + hf * 8;
                if (p0 + r >= P) continue;
                float v0 = acc[mt][nt][hf * 2];
                float v1 = acc[mt][nt][hf * 2 + 1];
                if (kind == 0) {
                    v0 += __ldg(&bias[oc]);
                    v1 += __ldg(&bias[oc + 1]);
                    size_t ob = (size_t)c_ao[lvl] + (size_t)(p0 + r) * 256 + oc;
                    float2 st = {v0, v1};
                    *(float2*)&outp[ob] = st;
                    if (sn[r]) { s1 += v0 + v1; q1 += v0 * v0 + v1 * v1; }
                    else       { s0 += v0 + v1; q0 += v0 * v0 + v1 * v1; }
                } else if (oc < OC) {
                    long long unit =
                        (long long)sn[r] * TP + c_lb[lvl] + syy[r] * W + sxx[r];
                    v0 += __ldg(&bias[oc]);
                    v1 += __ldg(&bias[oc + 1]);
                    if (path == 0) {
                        outp[unit * 80 + oc] = v0;
                        outp[unit * 80 + oc + 1] = v1;
                    } else {
                        if (c_relu[oc]) v0 = fmaxf(v0, 0.f);
                        if (c_relu[oc + 1]) v1 = fmaxf(v1, 0.f);
                        outp[c_base[oc] + unit * c_ctot[oc] + c_ch[oc]] = v0;
                        outp[c_base[oc + 1] + unit * c_ctot[oc + 1] + c_ch[oc + 1]] = v1;
                    }
                }
            }
        }
        if (kind == 0) {
#pragma unroll
            for (int o = 16; o > 0; o >>= 1) {
                s0 += __shfl_xor_sync(0xffffffffu, s0, o);
                q0 += __shfl_xor_sync(0xffffffffu, q0, o);
                s1 += __shfl_xor_sync(0xffffffffu, s1, o);
                q1 += __shfl_xor_sync(0xffffffffu, q1, o);
            }
            if (lane == 0) {
                int gb = path * 320 + lvl * 64 + ((oc0 + nwarp + nt * 8) >> 3);
                atomicAdd(&gsum[gb], s0);
                atomicAdd(&gsq[gb], q0);
                if (s1 != 0.f || q1 != 0.f) {
                    atomicAdd(&gsum[gb + 32], s1);
                    atomicAdd(&gsq[gb + 32], q1);
                }
            }
        }
    }
}

// ---------------------------------------------------------------------------
// GroupNorm apply: computes mu/inv from fused-epilogue sums.
// ---------------------------------------------------------------------------
__global__ void gn_apply(const float* __restrict__ y0, const float* __restrict__ y1,
                         __half* __restrict__ d0, __half* __restrict__ d1,
                         const float* __restrict__ gm0, const float* __restrict__ gm1,
                         const float* __restrict__ bt0, const float* __restrict__ bt1,
                         const float* __restrict__ gsum, const float* __restrict__ gsq) {
    int idx = blockIdx.x * blockDim.x + threadIdx.x;
    if (idx >= TOTE / 4) return;
    int pathv = blockIdx.y;
    const float* y = pathv ? y1 : y0;
    __half* act = pathv ? d1 : d0;
    const float* gamma = pathv ? gm1 : gm0;
    const float* beta = pathv ? bt1 : bt0;
    int e = idx * 4;
    int l = (e >= c_ao[1]) + (e >= c_ao[2]) + (e >= c_ao[3]) + (e >= c_ao[4]);
    int c = e & 255;
    int pl = (e - c_ao[l]) >> 8;
    int n = pl >= c_HWs[l] ? 1 : 0;
    int ng = pathv * 320 + l * 64 + n * 32 + (c >> 3);
    float M = 8.f * c_HWs[l];
    float sm = gsum[ng];
    float mu = sm / M;
    float iv = rsqrtf(gsq[ng] / M - mu * mu + 1e-5f);
    float4 v = *(const float4*)&y[e];
    float4 gmv = *(const float4*)&gamma[c];
    float4 btv = *(const float4*)&beta[c];
    __half2 h0 = __floats2half2_rn(fmaxf((v.x - mu) * iv * gmv.x + btv.x, 0.f),
                                   fmaxf((v.y - mu) * iv * gmv.y + btv.y, 0.f));
    __half2 h1 = __floats2half2_rn(fmaxf((v.z - mu) * iv * gmv.z + btv.z, 0.f),
                                   fmaxf((v.w - mu) * iv * gmv.w + btv.w, 0.f));
    uint2 st = {*(uint32_t*)&h0, *(uint32_t*)&h1};
    *(uint2*)&act[e] = st;
}

// ---------------------------------------------------------------------------
// Host orchestration
// ---------------------------------------------------------------------------
extern "C" void kernel_launch(void* const* d_in, const int* in_sizes, int n_in,
                              void* d_out, int out_size) {
    const float* feats[5];
    for (int i = 0; i < 5; i++) feats[i] = (const float*)d_in[i];
    const float* cls_conv_w = (const float*)d_in[5];
    const float* cls_conv_b = (const float*)d_in[6];
    const float* cls_gn_w = (const float*)d_in[7];
    const float* cls_gn_b = (const float*)d_in[8];
    const float* cls_out_w = (const float*)d_in[9];
    const float* cls_out_b = (const float*)d_in[10];
    const float* reg_conv_w = (const float*)d_in[11];
    const float* reg_conv_b = (const float*)d_in[12];
    const float* reg_gn_w = (const float*)d_in[13];
    const float* reg_gn_b = (const float*)d_in[14];
    float* out = (float*)d_out;

    __half *xh, *actA, *actB, *actC, *actD, *wtc, *wtr, *wtco, *wtro;
    float *ybuf, *ybuf2, *regw, *regb, *gsum, *gsq;
    cudaGetSymbolAddress((void**)&xh, g_xh);
    cudaGetSymbolAddress((void**)&actA, g_actA);
    cudaGetSymbolAddress((void**)&actB, g_actB);
    cudaGetSymbolAddress((void**)&actC, g_actC);
    cudaGetSymbolAddress((void**)&actD, g_actD);
    cudaGetSymbolAddress((void**)&ybuf, g_y);
    cudaGetSymbolAddress((void**)&ybuf2, g_y2);
    cudaGetSymbolAddress((void**)&regw, g_regw);
    cudaGetSymbolAddress((void**)&regb, g_regb);
    cudaGetSymbolAddress((void**)&wtc, g_wt_cls);
    cudaGetSymbolAddress((void**)&wtr, g_wt_reg);
    cudaGetSymbolAddress((void**)&wtco, g_wtc_out);
    cudaGetSymbolAddress((void**)&wtro, g_wtr_out);
    cudaGetSymbolAddress((void**)&gsum, g_gnsum);
    cudaGetSymbolAddress((void**)&gsq, g_gnsq);

    cudaFuncSetAttribute(gemm16, cudaFuncAttributeMaxDynamicSharedMemorySize,
                         DYN_SMEM);

    zero_stats<<<10, 256>>>();

    pack_reg<<<(26 * 2304 + 255) / 256, 256>>>(
        (const float*)d_in[15], (const float*)d_in[16],
        (const float*)d_in[17], (const float*)d_in[18],
        (const float*)d_in[19], (const float*)d_in[20],
        (const float*)d_in[21], (const float*)d_in[22],
        (const float*)d_in[23], (const float*)d_in[24],
        (const float*)d_in[25], (const float*)d_in[26]);

    int wtN = 4 * 9 * 256 * 256;
    pack_wt<<<(wtN + 255) / 256, 256>>>(cls_conv_w, wtc);
    pack_wt<<<(wtN + 255) / 256, 256>>>(reg_conv_w, wtr);
    int hN = 9 * 128 * 256;
    pack_headw<<<(hN + 255) / 256, 256>>>(cls_out_w, wtco, 80);
    pack_headw<<<(hN + 255) / 256, 256>>>(regw, wtro, 26);

    to_nhwc_half<<<dim3(475, 8, 10), dim3(32, 32)>>>(feats[0], feats[1], feats[2],
                                                     feats[3], feats[4], xh);

    int gApplyX = (TOTE / 4 + 255) / 256;
    const __half* curc = xh;
    const __half* curr = xh;
    __half* cd[4] = {actA, actB, actA, actB};
    __half* rd[4] = {actC, actD, actC, actD};
    for (int s = 0; s < 4; s++) {
        gemm16<<<dim3(NTILES, 4), 256, DYN_SMEM>>>(
            curc, curr, wtc + (size_t)s * 589824, wtr + (size_t)s * 589824,
            cls_conv_b + s * 256, reg_conv_b + s * 256, ybuf, ybuf2,
            gsum + s * 640, gsq + s * 640, 72, 0);
        gn_apply<<<dim3(gApplyX, 2), 256>>>(ybuf, ybuf2, cd[s], rd[s],
                                            cls_gn_w + s * 256, reg_gn_w + s * 256,
                                            cls_gn_b + s * 256, reg_gn_b + s * 256,
                                            gsum + s * 640, gsq + s * 640);
        curc = cd[s];
        curr = rd[s];
    }
    // heads: by 0 = cls (reads actB), by 1 = reg (reads actD)
    gemm16<<<dim3(NTILES, 2), 256, DYN_SMEM>>>(actB, actD, wtco, wtro, cls_out_b,
                                               regb, out, out, nullptr, nullptr,
                                               72, 1);
    (void)in_sizes; (void)n_in; (void)out_size;
}

// round 12
// speedup vs baseline: 1.7572x; 1.0059x over previous
#include <cuda_runtime.h>
#include <cuda_fp16.h>
#include <cstdint>

// ---------------------------------------------------------------------------
// FCOS head, fp16 mma.sync (m16n8k16, fp32 accum). Level+path batched,
// 4-deep cp.async ring (R6 config: 256 thr, warp tile 64x32).
// R9: GN stats fused into tower epilogue. R10: heads single fp16 pass.
// R11: GN scale/shift precomputed (gn_coef) -> gn_apply is MUFU-free;
// prologue packing consolidated into 2 launches.
// ---------------------------------------------------------------------------

#define TP 20267
#define TOTE 10376704          // total NHWC elements (all levels, both batch)
#define PAD 20                 // smem row pitch in uint32 words
#define NTILES 319             // total M-tiles over all levels
#define STAGE_BYTES 20480      // per pipeline slot: A(10240) + B(10240)
#define DYN_SMEM (4 * STAGE_BYTES)
#define WTN 2359296            // 4*9*256*256

__device__ __half g_xh[TOTE];
__device__ __half g_actA[TOTE];   // cls ping
__device__ __half g_actB[TOTE];   // cls pong
__device__ __half g_actC[TOTE];   // reg ping
__device__ __half g_actD[TOTE];   // reg pong
__device__ float  g_y[TOTE];      // cls conv out
__device__ float  g_y2[TOTE];     // reg conv out
__device__ float  g_gnsum[4 * 640];
__device__ float  g_gnsq[4 * 640];
__device__ float  g_scale[2 * 2560];
__device__ float  g_shift[2 * 2560];
__device__ float  g_regb[26];
__device__ __half g_wt_cls[WTN];                 // [s][tap][oc][ic]
__device__ __half g_wt_reg[WTN];
__device__ __half g_wtc_out[9 * 128 * 256];      // [tap][ocpad][ic]
__device__ __half g_wtr_out[9 * 128 * 256];

__constant__ int c_Hs[5] = {100, 50, 25, 13, 7};
__constant__ int c_Ws[5] = {152, 76, 38, 19, 10};
__constant__ int c_HWs[5] = {15200, 3800, 950, 247, 70};
__constant__ int c_Ps[5] = {30400, 7600, 1900, 494, 140};
__constant__ int c_tb[5] = {0, 238, 298, 313, 317};
__constant__ int c_ao[5] = {0, 7782400, 9728000, 10214400, 10340864};
__constant__ int c_lb[5] = {0, 15200, 19000, 19950, 20197};

__constant__ long long c_base[26] = {
    3242720LL, 3242720LL, 3242720LL, 3242720LL,
    3404856LL,
    3445390LL, 3445390LL, 3445390LL,
    3566992LL,
    3607526LL, 3607526LL, 3607526LL, 3607526LL, 3607526LL, 3607526LL,
    3607526LL, 3607526LL, 3607526LL, 3607526LL, 3607526LL, 3607526LL,
    3607526LL, 3607526LL, 3607526LL, 3607526LL,
    4256070LL};
__constant__ int c_ctot[26] = {4, 4, 4, 4, 1, 3, 3, 3, 1,
                               16, 16, 16, 16, 16, 16, 16, 16,
                               16, 16, 16, 16, 16, 16, 16, 16, 1};
__constant__ int c_ch[26] = {0, 1, 2, 3, 0, 0, 1, 2, 0,
                             0, 1, 2, 3, 4, 5, 6, 7,
                             8, 9, 10, 11, 12, 13, 14, 15, 0};
__constant__ int c_relu[26] = {1, 1, 1, 1, 0, 0, 0, 0, 0,
                               0, 0, 0, 0, 0, 0, 0, 0,
                               0, 0, 0, 0, 0, 0, 0, 0, 0};

__device__ __forceinline__ void cpa16p(uint32_t d, const void* s, int sz) {
    asm volatile("cp.async.cg.shared.global [%0], [%1], 16, %2;" ::"r"(d), "l"(s), "r"(sz));
}
#define LDSM4(r0, r1, r2, r3, a)                                           \
    asm volatile("ldmatrix.sync.aligned.m8n8.x4.shared.b16 {%0,%1,%2,%3}, [%4];" \
                 : "=r"(r0), "=r"(r1), "=r"(r2), "=r"(r3) : "r"(a))

// ---------------------------------------------------------------------------
// NCHW fp32 -> NHWC half, all levels in one launch. grid (475, 8, 10)
// ---------------------------------------------------------------------------
__global__ void to_nhwc_half(const float* __restrict__ f0, const float* __restrict__ f1,
                             const float* __restrict__ f2, const float* __restrict__ f3,
                             const float* __restrict__ f4, __half* __restrict__ xh) {
    __shared__ float t[32][33];
    int z = blockIdx.z;
    int lvl = z >> 1, n = z & 1;
    int HW = c_HWs[lvl];
    int p0 = blockIdx.x * 32;
    if (p0 >= HW) return;
    const float* src = lvl == 0 ? f0 : lvl == 1 ? f1 : lvl == 2 ? f2 : lvl == 3 ? f3 : f4;
    __half* dst = xh + c_ao[lvl];
    int c0 = blockIdx.y * 32;
    int tx = threadIdx.x, ty = threadIdx.y;
    int p = p0 + tx;
    if (p < HW) t[ty][tx] = src[((size_t)(n * 256 + c0 + ty)) * HW + p];
    __syncthreads();
    int p2 = p0 + ty, c2 = c0 + tx;
    if (p2 < HW) dst[((size_t)(n * HW + p2)) * 256 + c2] = __float2half_rn(t[tx][ty]);
}

// ---------------------------------------------------------------------------
// Consolidated weight packs
// ---------------------------------------------------------------------------
__global__ void pack_all_w(const float* __restrict__ wc, const float* __restrict__ wr) {
    int idx = blockIdx.x * blockDim.x + threadIdx.x;
    if (idx >= 2 * WTN) return;
    int which = idx >= WTN;
    int i = which ? idx - WTN : idx;
    const float* w = which ? wr : wc;
    __half* d = which ? g_wt_reg : g_wt_cls;
    int ic = i & 255;
    int oc = (i >> 8) & 255;
    int tap = (i >> 16) % 9;
    int s = i / 589824;
    d[i] = __float2half_rn(w[(((size_t)(s * 256 + oc) * 256 + ic) * 9) + tap]);
}

// heads (both), stat zeroing, reg bias — no inter-dependencies
__global__ void pack_small(
    const float* __restrict__ cls_out_w,
    const float* __restrict__ bbox_w, const float* __restrict__ bbox_b,
    const float* __restrict__ ctr_w,  const float* __restrict__ ctr_b,
    const float* __restrict__ dim_w,  const float* __restrict__ dim_b,
    const float* __restrict__ ori_w,  const float* __restrict__ ori_b,
    const float* __restrict__ kp_w,   const float* __restrict__ kp_b,
    const float* __restrict__ depth_w,const float* __restrict__ depth_b) {
    int idx = blockIdx.x * blockDim.x + threadIdx.x;
    const int HN = 9 * 128 * 256;   // 294912
    if (idx < HN) {
        // cls head: [tap][ocpad 128][ic]
        int ic = idx & 255;
        int oc = (idx >> 8) & 127;
        int tap = idx >> 15;
        float v = (oc < 80) ? cls_out_w[((size_t)oc * 256 + ic) * 9 + tap] : 0.f;
        g_wtc_out[idx] = __float2half_rn(v);
    } else if (idx < 2 * HN) {
        int i = idx - HN;
        int ic = i & 255;
        int oc = (i >> 8) & 127;
        int tap = i >> 15;
        float v = 0.f;
        if (oc < 26) {
            const float* src;
            if (oc < 4)       src = bbox_w + oc * 2304;
            else if (oc == 4) src = ctr_w;
            else if (oc < 8)  src = dim_w + (oc - 5) * 2304;
            else if (oc == 8) src = ori_w;
            else if (oc < 25) src = kp_w + (oc - 9) * 2304;
            else              src = depth_w;
            v = src[ic * 9 + tap];
        }
        g_wtr_out[i] = __float2half_rn(v);
    } else if (idx < 2 * HN + 2560) {
        g_gnsum[idx - 2 * HN] = 0.f;
    } else if (idx < 2 * HN + 5120) {
        g_gnsq[idx - 2 * HN - 2560] = 0.f;
    } else if (idx < 2 * HN + 5120 + 26) {
        int oc = idx - 2 * HN - 5120;
        float b;
        if (oc < 4)       b = bbox_b[oc];
        else if (oc == 4) b = ctr_b[0];
        else if (oc < 8)  b = dim_b[oc - 5];
        else if (oc == 8) b = ori_b[0];
        else if (oc < 25) b = kp_b[oc - 9];
        else              b = depth_b[0];
        g_regb[oc] = b;
    }
}

// ---------------------------------------------------------------------------
// Path+level-batched fp16 implicit-GEMM conv. M=128 pos x N=128 oc, 8 warps
// (warp tile 64x32). kind 0: towers, grid (NTILES,4); kind 1: heads,
// grid (NTILES,2). Tower epilogue also emits GN partial sums (gsum/gsq).
// ---------------------------------------------------------------------------
__global__ __launch_bounds__(256, 2) void gemm16(
    const __half* __restrict__ x0, const __half* __restrict__ x1,
    const __half* __restrict__ wt0, const __half* __restrict__ wt1,
    const float* __restrict__ b0p, const float* __restrict__ b1p,
    float* __restrict__ out0, float* __restrict__ out1,
    float* __restrict__ gsum, float* __restrict__ gsq, int NST, int kind) {
    extern __shared__ __align__(16) uint32_t dynsm[];
    __shared__ int syy[128], sxx[128], sn[128];

    int tid = threadIdx.x;
    int bx = blockIdx.x, by = blockIdx.y;
    int lvl = (bx >= c_tb[1]) + (bx >= c_tb[2]) + (bx >= c_tb[3]) + (bx >= c_tb[4]);
    int H = c_Hs[lvl], W = c_Ws[lvl], HW = c_HWs[lvl], P = c_Ps[lvl];
    int p0 = (bx - c_tb[lvl]) * 128;

    int path, oc0, OC;
    if (kind == 0) {
        path = by >> 1;
        oc0 = (by & 1) * 128;
        OC = 256;
    } else {
        path = by;
        oc0 = 0;
        OC = by ? 26 : 80;
    }
    const __half* x = (path ? x1 : x0) + c_ao[lvl];
    const __half* wt = path ? wt1 : wt0;
    const float* bias = path ? b1p : b0p;
    float* outp = path ? out1 : out0;

    if (tid < 128) {
        int p = p0 + tid;
        if (p < P) {
            int n = p >= HW ? 1 : 0;
            int rr = p - n * HW;
            int yy = rr / W;
            syy[tid] = yy;
            sxx[tid] = rr - yy * W;
            sn[tid] = n;
        } else {
            syy[tid] = -100000;
            sxx[tid] = -100000;
            sn[tid] = 0;
        }
    }
    __syncthreads();

    int warp = tid >> 5, lane = tid & 31, g = lane >> 2, t4 = lane & 3;
    int mwarp = (warp >> 2) * 64, nwarp = (warp & 3) * 32;

    float acc[4][4][4];
#pragma unroll
    for (int i = 0; i < 4; i++)
#pragma unroll
        for (int j = 0; j < 4; j++)
#pragma unroll
            for (int q = 0; q < 4; q++) acc[i][j][q] = 0.f;

    int m0 = tid >> 2, cw0 = tid & 3;
    uint32_t smbase = (uint32_t)__cvta_generic_to_shared(dynsm);

    // ldmatrix lane addressing (within a slot)
    int laneA_row = lane & 15;
    int colA = (lane >> 4) * 4;
    int laneB_row = ((lane >> 4) << 3) + (lane & 7);
    int colB = ((lane >> 3) & 1) * 4;
    uint32_t aAoff = ((mwarp + laneA_row) * PAD + colA) * 4;
    uint32_t aBoff = 10240 + ((nwarp + laneB_row) * PAD + colB) * 4;

    auto load_chunk = [&](int c, int slot) {
        int tap = c >> 3;
        int icc = (c & 7) << 5;
        int ty = tap / 3;
        int dy = ty - 1, dx = tap - ty * 3 - 1;
        uint32_t base = smbase + slot * STAGE_BYTES;
#pragma unroll
        for (int j = 0; j < 2; j++) {
            int m = m0 + j * 64;
            int gy = syy[m] + dy, gx = sxx[m] + dx;
            bool v = ((unsigned)gy < (unsigned)H) && ((unsigned)gx < (unsigned)W);
            const __half* src =
                x + ((size_t)(sn[m] * HW + gy * W + gx) * 256 + icc + cw0 * 8);
            cpa16p(base + (m * PAD + cw0 * 4) * 4, v ? src : (const __half*)x,
                   v ? 16 : 0);
        }
        const __half* wbase =
            kind ? wt + ((size_t)(tap * 128)) * 256
                 : wt + ((size_t)(tap * 256 + oc0)) * 256;
#pragma unroll
        for (int j = 0; j < 2; j++) {
            int ocr = m0 + j * 64;
            cpa16p(base + 10240 + (ocr * PAD + cw0 * 4) * 4,
                   wbase + (size_t)ocr * 256 + icc + cw0 * 8, 16);
        }
        asm volatile("cp.async.commit_group;");
    };

    load_chunk(0, 0);
    load_chunk(1, 1);
    load_chunk(2, 2);

    for (int s = 0; s < NST; s++) {
        int slot = s & 3;
        if (s + 2 < NST) {
            asm volatile("cp.async.wait_group 2;");
        } else if (s + 1 < NST) {
            asm volatile("cp.async.wait_group 1;");
        } else {
            asm volatile("cp.async.wait_group 0;");
        }
        __syncthreads();
        if (s + 3 < NST) load_chunk(s + 3, (s + 3) & 3);

        uint32_t sb = smbase + slot * STAGE_BYTES;
        uint32_t aA = sb + aAoff;
        uint32_t aB = sb + aBoff;
#pragma unroll
        for (int kb = 0; kb < 2; kb++) {
            uint32_t kwb = kb * 8 * 4;
            uint32_t A[4][4], Bv[2][4];
#pragma unroll
            for (int mt = 0; mt < 4; mt++)
                LDSM4(A[mt][0], A[mt][1], A[mt][2], A[mt][3],
                      aA + mt * (16 * PAD * 4) + kwb);
#pragma unroll
            for (int ntp = 0; ntp < 2; ntp++)
                LDSM4(Bv[ntp][0], Bv[ntp][1], Bv[ntp][2], Bv[ntp][3],
                      aB + ntp * (16 * PAD * 4) + kwb);
#pragma unroll
            for (int mt = 0; mt < 4; mt++)
#pragma unroll
                for (int nt = 0; nt < 4; nt++) {
                    int ntp = nt >> 1, j = nt & 1;
                    asm volatile(
                        "mma.sync.aligned.m16n8k16.row.col.f32.f16.f16.f32 "
                        "{%0,%1,%2,%3}, {%4,%5,%6,%7}, {%8,%9}, {%0,%1,%2,%3};"
                        : "+f"(acc[mt][nt][0]), "+f"(acc[mt][nt][1]),
                          "+f"(acc[mt][nt][2]), "+f"(acc[mt][nt][3])
                        : "r"(A[mt][0]), "r"(A[mt][1]), "r"(A[mt][2]), "r"(A[mt][3]),
                          "r"(Bv[ntp][j * 2]), "r"(Bv[ntp][j * 2 + 1]));
                }
        }
    }

    // epilogue
#pragma unroll
    for (int nt = 0; nt < 4; nt++) {
        int oc = oc0 + nwarp + nt * 8 + 2 * t4;
        float s0 = 0.f, q0 = 0.f, s1 = 0.f, q1 = 0.f;
#pragma unroll
        for (int mt = 0; mt < 4; mt++) {
#pragma unroll
            for (int hf = 0; hf < 2; hf++) {
                int r = mwarp + mt * 16 + g + hf * 8;
                if (p0 + r >= P) continue;
                float v0 = acc[mt][nt][hf * 2];
                float v1 = acc[mt][nt][hf * 2 + 1];
                if (kind == 0) {
                    v0 += __ldg(&bias[oc]);
                    v1 += __ldg(&bias[oc + 1]);
                    size_t ob = (size_t)c_ao[lvl] + (size_t)(p0 + r) * 256 + oc;
                    float2 st = {v0, v1};
                    *(float2*)&outp[ob] = st;
                    if (sn[r]) { s1 += v0 + v1; q1 += v0 * v0 + v1 * v1; }
                    else       { s0 += v0 + v1; q0 += v0 * v0 + v1 * v1; }
                } else if (oc < OC) {
                    long long unit =
                        (long long)sn[r] * TP + c_lb[lvl] + syy[r] * W + sxx[r];
                    v0 += __ldg(&bias[oc]);
                    v1 += __ldg(&bias[oc + 1]);
                    if (path == 0) {
                        outp[unit * 80 + oc] = v0;
                        outp[unit * 80 + oc + 1] = v1;
                    } else {
                        if (c_relu[oc]) v0 = fmaxf(v0, 0.f);
                        if (c_relu[oc + 1]) v1 = fmaxf(v1, 0.f);
                        outp[c_base[oc] + unit * c_ctot[oc] + c_ch[oc]] = v0;
                        outp[c_base[oc + 1] + unit * c_ctot[oc + 1] + c_ch[oc + 1]] = v1;
                    }
                }
            }
        }
        if (kind == 0) {
#pragma unroll
            for (int o = 16; o > 0; o >>= 1) {
                s0 += __shfl_xor_sync(0xffffffffu, s0, o);
                q0 += __shfl_xor_sync(0xffffffffu, q0, o);
                s1 += __shfl_xor_sync(0xffffffffu, s1, o);
                q1 += __shfl_xor_sync(0xffffffffu, q1, o);
            }
            if (lane == 0) {
                int gb = path * 320 + lvl * 64 + ((oc0 + nwarp + nt * 8) >> 3);
                atomicAdd(&gsum[gb], s0);
                atomicAdd(&gsq[gb], q0);
                if (s1 != 0.f || q1 != 0.f) {
                    atomicAdd(&gsum[gb + 32], s1);
                    atomicAdd(&gsq[gb + 32], q1);
                }
            }
        }
    }
}

// ---------------------------------------------------------------------------
// GN coefficients: 640 rsqrt total, expands to per-channel scale/shift.
// ---------------------------------------------------------------------------
__global__ void gn_coef(const float* __restrict__ gsum, const float* __restrict__ gsq,
                        const float* __restrict__ gm0, const float* __restrict__ gm1,
                        const float* __restrict__ bt0, const float* __restrict__ bt1) {
    int ng = blockIdx.x * blockDim.x + threadIdx.x;
    if (ng >= 640) return;
    int path = ng >= 320;
    int b2 = ng - path * 320;
    int l = b2 >> 6;
    int r = b2 & 63;
    int n = r >> 5, gr = r & 31;
    float M = 8.f * c_HWs[l];
    float mu = gsum[ng] / M;
    float iv = rsqrtf(gsq[ng] / M - mu * mu + 1e-5f);
    const float* gam = path ? gm1 : gm0;
    const float* bet = path ? bt1 : bt0;
    int base = path * 2560 + l * 512 + n * 256 + gr * 8;
#pragma unroll
    for (int j = 0; j < 8; j++) {
        int c = gr * 8 + j;
        float s = iv * gam[c];
        g_scale[base + j] = s;
        g_shift[base + j] = bet[c] - mu * s;
    }
}

// ---------------------------------------------------------------------------
// GroupNorm apply: v*scale + shift, relu, to half. MUFU-free.
// ---------------------------------------------------------------------------
__global__ void gn_apply(const float* __restrict__ y0, const float* __restrict__ y1,
                         __half* __restrict__ d0, __half* __restrict__ d1) {
    int idx = blockIdx.x * blockDim.x + threadIdx.x;
    if (idx >= TOTE / 4) return;
    int pathv = blockIdx.y;
    const float* y = pathv ? y1 : y0;
    __half* act = pathv ? d1 : d0;
    int e = idx * 4;
    int l = (e >= c_ao[1]) + (e >= c_ao[2]) + (e >= c_ao[3]) + (e >= c_ao[4]);
    int c = e & 255;
    int pl = (e - c_ao[l]) >> 8;
    int n = pl >= c_HWs[l] ? 1 : 0;
    int cb = pathv * 2560 + l * 512 + n * 256 + c;
    float4 sc = *(const float4*)&g_scale[cb];
    float4 sh = *(const float4*)&g_shift[cb];
    float4 v = *(const float4*)&y[e];
    __half2 h0 = __floats2half2_rn(fmaxf(v.x * sc.x + sh.x, 0.f),
                                   fmaxf(v.y * sc.y + sh.y, 0.f));
    __half2 h1 = __floats2half2_rn(fmaxf(v.z * sc.z + sh.z, 0.f),
                                   fmaxf(v.w * sc.w + sh.w, 0.f));
    uint2 st = {*(uint32_t*)&h0, *(uint32_t*)&h1};
    *(uint2*)&act[e] = st;
}

// ---------------------------------------------------------------------------
// Host orchestration
// ---------------------------------------------------------------------------
extern "C" void kernel_launch(void* const* d_in, const int* in_sizes, int n_in,
                              void* d_out, int out_size) {
    const float* feats[5];
    for (int i = 0; i < 5; i++) feats[i] = (const float*)d_in[i];
    const float* cls_conv_w = (const float*)d_in[5];
    const float* cls_conv_b = (const float*)d_in[6];
    const float* cls_gn_w = (const float*)d_in[7];
    const float* cls_gn_b = (const float*)d_in[8];
    const float* cls_out_w = (const float*)d_in[9];
    const float* cls_out_b = (const float*)d_in[10];
    const float* reg_conv_w = (const float*)d_in[11];
    const float* reg_conv_b = (const float*)d_in[12];
    const float* reg_gn_w = (const float*)d_in[13];
    const float* reg_gn_b = (const float*)d_in[14];
    float* out = (float*)d_out;

    __half *xh, *actA, *actB, *actC, *actD, *wtc, *wtr, *wtco, *wtro;
    float *ybuf, *ybuf2, *regb, *gsum, *gsq;
    cudaGetSymbolAddress((void**)&xh, g_xh);
    cudaGetSymbolAddress((void**)&actA, g_actA);
    cudaGetSymbolAddress((void**)&actB, g_actB);
    cudaGetSymbolAddress((void**)&actC, g_actC);
    cudaGetSymbolAddress((void**)&actD, g_actD);
    cudaGetSymbolAddress((void**)&ybuf, g_y);
    cudaGetSymbolAddress((void**)&ybuf2, g_y2);
    cudaGetSymbolAddress((void**)&regb, g_regb);
    cudaGetSymbolAddress((void**)&wtc, g_wt_cls);
    cudaGetSymbolAddress((void**)&wtr, g_wt_reg);
    cudaGetSymbolAddress((void**)&wtco, g_wtc_out);
    cudaGetSymbolAddress((void**)&wtro, g_wtr_out);
    cudaGetSymbolAddress((void**)&gsum, g_gnsum);
    cudaGetSymbolAddress((void**)&gsq, g_gnsq);

    cudaFuncSetAttribute(gemm16, cudaFuncAttributeMaxDynamicSharedMemorySize,
                         DYN_SMEM);

    pack_all_w<<<(2 * WTN + 255) / 256, 256>>>(cls_conv_w, reg_conv_w);
    {
        int tot = 2 * 9 * 128 * 256 + 5120 + 26;
        pack_small<<<(tot + 255) / 256, 256>>>(
            cls_out_w,
            (const float*)d_in[15], (const float*)d_in[16],
            (const float*)d_in[17], (const float*)d_in[18],
            (const float*)d_in[19], (const float*)d_in[20],
            (const float*)d_in[21], (const float*)d_in[22],
            (const float*)d_in[23], (const float*)d_in[24],
            (const float*)d_in[25], (const float*)d_in[26]);
    }

    to_nhwc_half<<<dim3(475, 8, 10), dim3(32, 32)>>>(feats[0], feats[1], feats[2],
                                                     feats[3], feats[4], xh);

    int gApplyX = (TOTE / 4 + 255) / 256;
    const __half* curc = xh;
    const __half* curr = xh;
    __half* cd[4] = {actA, actB, actA, actB};
    __half* rd[4] = {actC, actD, actC, actD};
    for (int s = 0; s < 4; s++) {
        gemm16<<<dim3(NTILES, 4), 256, DYN_SMEM>>>(
            curc, curr, wtc + (size_t)s * 589824, wtr + (size_t)s * 589824,
            cls_conv_b + s * 256, reg_conv_b + s * 256, ybuf, ybuf2,
            gsum + s * 640, gsq + s * 640, 72, 0);
        gn_coef<<<3, 256>>>(gsum + s * 640, gsq + s * 640,
                            cls_gn_w + s * 256, reg_gn_w + s * 256,
                            cls_gn_b + s * 256, reg_gn_b + s * 256);
        gn_apply<<<dim3(gApplyX, 2), 256>>>(ybuf, ybuf2, cd[s], rd[s]);
        curc = cd[s];
        curr = rd[s];
    }
    // heads: by 0 = cls (reads actB), by 1 = reg (reads actD)
    gemm16<<<dim3(NTILES, 2), 256, DYN_SMEM>>>(actB, actD, wtco, wtro, cls_out_b,
                                               regb, out, out, nullptr, nullptr,
                                               72, 1);
    (void)in_sizes; (void)n_in; (void)out_size;
}

// round 13
// speedup vs baseline: 2.0358x; 1.1586x over previous
#include <cuda_runtime.h>
#include <cuda_fp16.h>
#include <cstdint>

// ---------------------------------------------------------------------------
// FCOS head, fp16 mma.sync (m16n8k16, fp32 accum). Level-batched,
// 4-deep cp.async ring (R6 config: 256 thr, warp tile 64x32).
// R9: GN stats fused in tower epilogue. R10: heads single pass.
// R11: GN coef tables. R12: cls/reg chains split per-path and run on two
// streams (fork/join events) to backfill wave-quantization idle slots.
// ---------------------------------------------------------------------------

#define TP 20267
#define TOTE 10376704
#define PAD 20
#define NTILES 319
#define STAGE_BYTES 20480
#define DYN_SMEM (4 * STAGE_BYTES)
#define WTN 2359296            // 4*9*256*256

__device__ __half g_xh[TOTE];
__device__ __half g_actA[TOTE];   // cls ping
__device__ __half g_actB[TOTE];   // cls pong
__device__ __half g_actC[TOTE];   // reg ping
__device__ __half g_actD[TOTE];   // reg pong
__device__ float  g_y[TOTE];      // cls conv out
__device__ float  g_y2[TOTE];     // reg conv out
__device__ float  g_gnsum[4 * 640];
__device__ float  g_gnsq[4 * 640];
__device__ float  g_scale[2 * 2560];
__device__ float  g_shift[2 * 2560];
__device__ float  g_regb[26];
__device__ __half g_wt_cls[WTN];                 // [s][tap][oc][ic]
__device__ __half g_wt_reg[WTN];
__device__ __half g_wtc_out[9 * 128 * 256];      // [tap][ocpad][ic]
__device__ __half g_wtr_out[9 * 128 * 256];

__constant__ int c_Hs[5] = {100, 50, 25, 13, 7};
__constant__ int c_Ws[5] = {152, 76, 38, 19, 10};
__constant__ int c_HWs[5] = {15200, 3800, 950, 247, 70};
__constant__ int c_Ps[5] = {30400, 7600, 1900, 494, 140};
__constant__ int c_tb[5] = {0, 238, 298, 313, 317};
__constant__ int c_ao[5] = {0, 7782400, 9728000, 10214400, 10340864};
__constant__ int c_lb[5] = {0, 15200, 19000, 19950, 20197};

__constant__ long long c_base[26] = {
    3242720LL, 3242720LL, 3242720LL, 3242720LL,
    3404856LL,
    3445390LL, 3445390LL, 3445390LL,
    3566992LL,
    3607526LL, 3607526LL, 3607526LL, 3607526LL, 3607526LL, 3607526LL,
    3607526LL, 3607526LL, 3607526LL, 3607526LL, 3607526LL, 3607526LL,
    3607526LL, 3607526LL, 3607526LL, 3607526LL,
    4256070LL};
__constant__ int c_ctot[26] = {4, 4, 4, 4, 1, 3, 3, 3, 1,
                               16, 16, 16, 16, 16, 16, 16, 16,
                               16, 16, 16, 16, 16, 16, 16, 16, 1};
__constant__ int c_ch[26] = {0, 1, 2, 3, 0, 0, 1, 2, 0,
                             0, 1, 2, 3, 4, 5, 6, 7,
                             8, 9, 10, 11, 12, 13, 14, 15, 0};
__constant__ int c_relu[26] = {1, 1, 1, 1, 0, 0, 0, 0, 0,
                               0, 0, 0, 0, 0, 0, 0, 0,
                               0, 0, 0, 0, 0, 0, 0, 0, 0};

__device__ __forceinline__ void cpa16p(uint32_t d, const void* s, int sz) {
    asm volatile("cp.async.cg.shared.global [%0], [%1], 16, %2;" ::"r"(d), "l"(s), "r"(sz));
}
#define LDSM4(r0, r1, r2, r3, a)                                           \
    asm volatile("ldmatrix.sync.aligned.m8n8.x4.shared.b16 {%0,%1,%2,%3}, [%4];" \
                 : "=r"(r0), "=r"(r1), "=r"(r2), "=r"(r3) : "r"(a))

// ---------------------------------------------------------------------------
// NCHW fp32 -> NHWC half, all levels in one launch. grid (475, 8, 10)
// ---------------------------------------------------------------------------
__global__ void to_nhwc_half(const float* __restrict__ f0, const float* __restrict__ f1,
                             const float* __restrict__ f2, const float* __restrict__ f3,
                             const float* __restrict__ f4, __half* __restrict__ xh) {
    __shared__ float t[32][33];
    int z = blockIdx.z;
    int lvl = z >> 1, n = z & 1;
    int HW = c_HWs[lvl];
    int p0 = blockIdx.x * 32;
    if (p0 >= HW) return;
    const float* src = lvl == 0 ? f0 : lvl == 1 ? f1 : lvl == 2 ? f2 : lvl == 3 ? f3 : f4;
    __half* dst = xh + c_ao[lvl];
    int c0 = blockIdx.y * 32;
    int tx = threadIdx.x, ty = threadIdx.y;
    int p = p0 + tx;
    if (p < HW) t[ty][tx] = src[((size_t)(n * 256 + c0 + ty)) * HW + p];
    __syncthreads();
    int p2 = p0 + ty, c2 = c0 + tx;
    if (p2 < HW) dst[((size_t)(n * HW + p2)) * 256 + c2] = __float2half_rn(t[tx][ty]);
}

// ---------------------------------------------------------------------------
// Consolidated weight packs
// ---------------------------------------------------------------------------
__global__ void pack_all_w(const float* __restrict__ wc, const float* __restrict__ wr) {
    int idx = blockIdx.x * blockDim.x + threadIdx.x;
    if (idx >= 2 * WTN) return;
    int which = idx >= WTN;
    int i = which ? idx - WTN : idx;
    const float* w = which ? wr : wc;
    __half* d = which ? g_wt_reg : g_wt_cls;
    int ic = i & 255;
    int oc = (i >> 8) & 255;
    int tap = (i >> 16) % 9;
    int s = i / 589824;
    d[i] = __float2half_rn(w[(((size_t)(s * 256 + oc) * 256 + ic) * 9) + tap]);
}

__global__ void pack_small(
    const float* __restrict__ cls_out_w,
    const float* __restrict__ bbox_w, const float* __restrict__ bbox_b,
    const float* __restrict__ ctr_w,  const float* __restrict__ ctr_b,
    const float* __restrict__ dim_w,  const float* __restrict__ dim_b,
    const float* __restrict__ ori_w,  const float* __restrict__ ori_b,
    const float* __restrict__ kp_w,   const float* __restrict__ kp_b,
    const float* __restrict__ depth_w,const float* __restrict__ depth_b) {
    int idx = blockIdx.x * blockDim.x + threadIdx.x;
    const int HN = 9 * 128 * 256;
    if (idx < HN) {
        int ic = idx & 255;
        int oc = (idx >> 8) & 127;
        int tap = idx >> 15;
        float v = (oc < 80) ? cls_out_w[((size_t)oc * 256 + ic) * 9 + tap] : 0.f;
        g_wtc_out[idx] = __float2half_rn(v);
    } else if (idx < 2 * HN) {
        int i = idx - HN;
        int ic = i & 255;
        int oc = (i >> 8) & 127;
        int tap = i >> 15;
        float v = 0.f;
        if (oc < 26) {
            const float* src;
            if (oc < 4)       src = bbox_w + oc * 2304;
            else if (oc == 4) src = ctr_w;
            else if (oc < 8)  src = dim_w + (oc - 5) * 2304;
            else if (oc == 8) src = ori_w;
            else if (oc < 25) src = kp_w + (oc - 9) * 2304;
            else              src = depth_w;
            v = src[ic * 9 + tap];
        }
        g_wtr_out[i] = __float2half_rn(v);
    } else if (idx < 2 * HN + 2560) {
        g_gnsum[idx - 2 * HN] = 0.f;
    } else if (idx < 2 * HN + 5120) {
        g_gnsq[idx - 2 * HN - 2560] = 0.f;
    } else if (idx < 2 * HN + 5120 + 26) {
        int oc = idx - 2 * HN - 5120;
        float b;
        if (oc < 4)       b = bbox_b[oc];
        else if (oc == 4) b = ctr_b[0];
        else if (oc < 8)  b = dim_b[oc - 5];
        else if (oc == 8) b = ori_b[0];
        else if (oc < 25) b = kp_b[oc - 9];
        else              b = depth_b[0];
        g_regb[oc] = b;
    }
}

// ---------------------------------------------------------------------------
// Per-path fp16 implicit-GEMM conv. M=128 pos x N=128 oc, 8 warps
// (warp tile 64x32). kind 0: tower, grid (NTILES,2) (by = oc half);
// kind 1: head, grid (NTILES,1). path selects output layout for heads.
// ---------------------------------------------------------------------------
__global__ __launch_bounds__(256, 2) void gemm16(
    const __half* __restrict__ xg, const __half* __restrict__ wt,
    const float* __restrict__ bias, float* __restrict__ outp,
    float* __restrict__ gsum, float* __restrict__ gsq, int NST, int kind,
    int path) {
    extern __shared__ __align__(16) uint32_t dynsm[];
    __shared__ int syy[128], sxx[128], sn[128];

    int tid = threadIdx.x;
    int bx = blockIdx.x, by = blockIdx.y;
    int lvl = (bx >= c_tb[1]) + (bx >= c_tb[2]) + (bx >= c_tb[3]) + (bx >= c_tb[4]);
    int H = c_Hs[lvl], W = c_Ws[lvl], HW = c_HWs[lvl], P = c_Ps[lvl];
    int p0 = (bx - c_tb[lvl]) * 128;

    int oc0, OC;
    if (kind == 0) { oc0 = by * 128; OC = 256; }
    else           { oc0 = 0; OC = path ? 26 : 80; }
    const __half* x = xg + c_ao[lvl];

    if (tid < 128) {
        int p = p0 + tid;
        if (p < P) {
            int n = p >= HW ? 1 : 0;
            int rr = p - n * HW;
            int yy = rr / W;
            syy[tid] = yy;
            sxx[tid] = rr - yy * W;
            sn[tid] = n;
        } else {
            syy[tid] = -100000;
            sxx[tid] = -100000;
            sn[tid] = 0;
        }
    }
    __syncthreads();

    int warp = tid >> 5, lane = tid & 31, g = lane >> 2, t4 = lane & 3;
    int mwarp = (warp >> 2) * 64, nwarp = (warp & 3) * 32;

    float acc[4][4][4];
#pragma unroll
    for (int i = 0; i < 4; i++)
#pragma unroll
        for (int j = 0; j < 4; j++)
#pragma unroll
            for (int q = 0; q < 4; q++) acc[i][j][q] = 0.f;

    int m0 = tid >> 2, cw0 = tid & 3;
    uint32_t smbase = (uint32_t)__cvta_generic_to_shared(dynsm);

    int laneA_row = lane & 15;
    int colA = (lane >> 4) * 4;
    int laneB_row = ((lane >> 4) << 3) + (lane & 7);
    int colB = ((lane >> 3) & 1) * 4;
    uint32_t aAoff = ((mwarp + laneA_row) * PAD + colA) * 4;
    uint32_t aBoff = 10240 + ((nwarp + laneB_row) * PAD + colB) * 4;

    auto load_chunk = [&](int c, int slot) {
        int tap = c >> 3;
        int icc = (c & 7) << 5;
        int ty = tap / 3;
        int dy = ty - 1, dx = tap - ty * 3 - 1;
        uint32_t base = smbase + slot * STAGE_BYTES;
#pragma unroll
        for (int j = 0; j < 2; j++) {
            int m = m0 + j * 64;
            int gy = syy[m] + dy, gx = sxx[m] + dx;
            bool v = ((unsigned)gy < (unsigned)H) && ((unsigned)gx < (unsigned)W);
            const __half* src =
                x + ((size_t)(sn[m] * HW + gy * W + gx) * 256 + icc + cw0 * 8);
            cpa16p(base + (m * PAD + cw0 * 4) * 4, v ? src : (const __half*)x,
                   v ? 16 : 0);
        }
        const __half* wbase =
            kind ? wt + ((size_t)(tap * 128)) * 256
                 : wt + ((size_t)(tap * 256 + oc0)) * 256;
#pragma unroll
        for (int j = 0; j < 2; j++) {
            int ocr = m0 + j * 64;
            cpa16p(base + 10240 + (ocr * PAD + cw0 * 4) * 4,
                   wbase + (size_t)ocr * 256 + icc + cw0 * 8, 16);
        }
        asm volatile("cp.async.commit_group;");
    };

    load_chunk(0, 0);
    load_chunk(1, 1);
    load_chunk(2, 2);

    for (int s = 0; s < NST; s++) {
        int slot = s & 3;
        if (s + 2 < NST) {
            asm volatile("cp.async.wait_group 2;");
        } else if (s + 1 < NST) {
            asm volatile("cp.async.wait_group 1;");
        } else {
            asm volatile("cp.async.wait_group 0;");
        }
        __syncthreads();
        if (s + 3 < NST) load_chunk(s + 3, (s + 3) & 3);

        uint32_t sb = smbase + slot * STAGE_BYTES;
        uint32_t aA = sb + aAoff;
        uint32_t aB = sb + aBoff;
#pragma unroll
        for (int kb = 0; kb < 2; kb++) {
            uint32_t kwb = kb * 8 * 4;
            uint32_t A[4][4], Bv[2][4];
#pragma unroll
            for (int mt = 0; mt < 4; mt++)
                LDSM4(A[mt][0], A[mt][1], A[mt][2], A[mt][3],
                      aA + mt * (16 * PAD * 4) + kwb);
#pragma unroll
            for (int ntp = 0; ntp < 2; ntp++)
                LDSM4(Bv[ntp][0], Bv[ntp][1], Bv[ntp][2], Bv[ntp][3],
                      aB + ntp * (16 * PAD * 4) + kwb);
#pragma unroll
            for (int mt = 0; mt < 4; mt++)
#pragma unroll
                for (int nt = 0; nt < 4; nt++) {
                    int ntp = nt >> 1, j = nt & 1;
                    asm volatile(
                        "mma.sync.aligned.m16n8k16.row.col.f32.f16.f16.f32 "
                        "{%0,%1,%2,%3}, {%4,%5,%6,%7}, {%8,%9}, {%0,%1,%2,%3};"
                        : "+f"(acc[mt][nt][0]), "+f"(acc[mt][nt][1]),
                          "+f"(acc[mt][nt][2]), "+f"(acc[mt][nt][3])
                        : "r"(A[mt][0]), "r"(A[mt][1]), "r"(A[mt][2]), "r"(A[mt][3]),
                          "r"(Bv[ntp][j * 2]), "r"(Bv[ntp][j * 2 + 1]));
                }
        }
    }

    // epilogue
#pragma unroll
    for (int nt = 0; nt < 4; nt++) {
        int oc = oc0 + nwarp + nt * 8 + 2 * t4;
        float s0 = 0.f, q0 = 0.f, s1 = 0.f, q1 = 0.f;
#pragma unroll
        for (int mt = 0; mt < 4; mt++) {
#pragma unroll
            for (int hf = 0; hf < 2; hf++) {
                int r = mwarp + mt * 16 + g + hf * 8;
                if (p0 + r >= P) continue;
                float v0 = acc[mt][nt][hf * 2];
                float v1 = acc[mt][nt][hf * 2 + 1];
                if (kind == 0) {
                    v0 += __ldg(&bias[oc]);
                    v1 += __ldg(&bias[oc + 1]);
                    size_t ob = (size_t)c_ao[lvl] + (size_t)(p0 + r) * 256 + oc;
                    float2 st = {v0, v1};
                    *(float2*)&outp[ob] = st;
                    if (sn[r]) { s1 += v0 + v1; q1 += v0 * v0 + v1 * v1; }
                    else       { s0 += v0 + v1; q0 += v0 * v0 + v1 * v1; }
                } else if (oc < OC) {
                    long long unit =
                        (long long)sn[r] * TP + c_lb[lvl] + syy[r] * W + sxx[r];
                    v0 += __ldg(&bias[oc]);
                    v1 += __ldg(&bias[oc + 1]);
                    if (path == 0) {
                        outp[unit * 80 + oc] = v0;
                        outp[unit * 80 + oc + 1] = v1;
                    } else {
                        bool two = (oc + 1) < OC;
                        if (c_relu[oc]) v0 = fmaxf(v0, 0.f);
                        outp[c_base[oc] + unit * c_ctot[oc] + c_ch[oc]] = v0;
                        if (two) {
                            if (c_relu[oc + 1]) v1 = fmaxf(v1, 0.f);
                            outp[c_base[oc + 1] + unit * c_ctot[oc + 1] +
                                 c_ch[oc + 1]] = v1;
                        }
                    }
                }
            }
        }
        if (kind == 0) {
#pragma unroll
            for (int o = 16; o > 0; o >>= 1) {
                s0 += __shfl_xor_sync(0xffffffffu, s0, o);
                q0 += __shfl_xor_sync(0xffffffffu, q0, o);
                s1 += __shfl_xor_sync(0xffffffffu, s1, o);
                q1 += __shfl_xor_sync(0xffffffffu, q1, o);
            }
            if (lane == 0) {
                int gb = lvl * 64 + ((oc0 + nwarp + nt * 8) >> 3);
                atomicAdd(&gsum[gb], s0);
                atomicAdd(&gsq[gb], q0);
                if (s1 != 0.f || q1 != 0.f) {
                    atomicAdd(&gsum[gb + 32], s1);
                    atomicAdd(&gsq[gb + 32], q1);
                }
            }
        }
    }
}

// ---------------------------------------------------------------------------
// GN coefficients per path: 320 groups -> per-channel scale/shift.
// ---------------------------------------------------------------------------
__global__ void gn_coef(const float* __restrict__ gsum, const float* __restrict__ gsq,
                        const float* __restrict__ gam, const float* __restrict__ bet,
                        float* __restrict__ scl, float* __restrict__ shf) {
    int ng = blockIdx.x * blockDim.x + threadIdx.x;
    if (ng >= 320) return;
    int l = ng >> 6;
    int r = ng & 63;
    int n = r >> 5, gr = r & 31;
    float M = 8.f * c_HWs[l];
    float mu = gsum[ng] / M;
    float iv = rsqrtf(gsq[ng] / M - mu * mu + 1e-5f);
    int base = l * 512 + n * 256 + gr * 8;
#pragma unroll
    for (int j = 0; j < 8; j++) {
        int c = gr * 8 + j;
        float s = iv * gam[c];
        scl[base + j] = s;
        shf[base + j] = bet[c] - mu * s;
    }
}

// ---------------------------------------------------------------------------
// GroupNorm apply (per path): v*scale + shift, relu, to half.
// ---------------------------------------------------------------------------
__global__ void gn_apply(const float* __restrict__ y, __half* __restrict__ act,
                         const float* __restrict__ scl, const float* __restrict__ shf) {
    int idx = blockIdx.x * blockDim.x + threadIdx.x;
    if (idx >= TOTE / 4) return;
    int e = idx * 4;
    int l = (e >= c_ao[1]) + (e >= c_ao[2]) + (e >= c_ao[3]) + (e >= c_ao[4]);
    int c = e & 255;
    int pl = (e - c_ao[l]) >> 8;
    int n = pl >= c_HWs[l] ? 1 : 0;
    int cb = l * 512 + n * 256 + c;
    float4 sc = *(const float4*)&scl[cb];
    float4 sh = *(const float4*)&shf[cb];
    float4 v = *(const float4*)&y[e];
    __half2 h0 = __floats2half2_rn(fmaxf(v.x * sc.x + sh.x, 0.f),
                                   fmaxf(v.y * sc.y + sh.y, 0.f));
    __half2 h1 = __floats2half2_rn(fmaxf(v.z * sc.z + sh.z, 0.f),
                                   fmaxf(v.w * sc.w + sh.w, 0.f));
    uint2 st = {*(uint32_t*)&h0, *(uint32_t*)&h1};
    *(uint2*)&act[e] = st;
}

// ---------------------------------------------------------------------------
// Host orchestration: cls chain on default stream, reg chain on side stream.
// ---------------------------------------------------------------------------
extern "C" void kernel_launch(void* const* d_in, const int* in_sizes, int n_in,
                              void* d_out, int out_size) {
    const float* feats[5];
    for (int i = 0; i < 5; i++) feats[i] = (const float*)d_in[i];
    const float* cls_conv_w = (const float*)d_in[5];
    const float* cls_conv_b = (const float*)d_in[6];
    const float* cls_gn_w = (const float*)d_in[7];
    const float* cls_gn_b = (const float*)d_in[8];
    const float* cls_out_w = (const float*)d_in[9];
    const float* cls_out_b = (const float*)d_in[10];
    const float* reg_conv_w = (const float*)d_in[11];
    const float* reg_conv_b = (const float*)d_in[12];
    const float* reg_gn_w = (const float*)d_in[13];
    const float* reg_gn_b = (const float*)d_in[14];
    float* out = (float*)d_out;

    __half *xh, *actA, *actB, *actC, *actD, *wtc, *wtr, *wtco, *wtro;
    float *ybuf, *ybuf2, *regb, *gsum, *gsq, *scl, *shf;
    cudaGetSymbolAddress((void**)&xh, g_xh);
    cudaGetSymbolAddress((void**)&actA, g_actA);
    cudaGetSymbolAddress((void**)&actB, g_actB);
    cudaGetSymbolAddress((void**)&actC, g_actC);
    cudaGetSymbolAddress((void**)&actD, g_actD);
    cudaGetSymbolAddress((void**)&ybuf, g_y);
    cudaGetSymbolAddress((void**)&ybuf2, g_y2);
    cudaGetSymbolAddress((void**)&regb, g_regb);
    cudaGetSymbolAddress((void**)&wtc, g_wt_cls);
    cudaGetSymbolAddress((void**)&wtr, g_wt_reg);
    cudaGetSymbolAddress((void**)&wtco, g_wtc_out);
    cudaGetSymbolAddress((void**)&wtro, g_wtr_out);
    cudaGetSymbolAddress((void**)&gsum, g_gnsum);
    cudaGetSymbolAddress((void**)&gsq, g_gnsq);
    cudaGetSymbolAddress((void**)&scl, g_scale);
    cudaGetSymbolAddress((void**)&shf, g_shift);

    cudaFuncSetAttribute(gemm16, cudaFuncAttributeMaxDynamicSharedMemorySize,
                         DYN_SMEM);

    // One-time resources (identical launch sequence every call).
    static cudaStream_t s1 = nullptr;
    static cudaEvent_t eF = nullptr, eJ = nullptr;
    if (!s1) {
        cudaStreamCreateWithFlags(&s1, cudaStreamNonBlocking);
        cudaEventCreateWithFlags(&eF, cudaEventDisableTiming);
        cudaEventCreateWithFlags(&eJ, cudaEventDisableTiming);
    }

    // prologue (default stream)
    pack_all_w<<<(2 * WTN + 255) / 256, 256>>>(cls_conv_w, reg_conv_w);
    {
        int tot = 2 * 9 * 128 * 256 + 5120 + 26;
        pack_small<<<(tot + 255) / 256, 256>>>(
            cls_out_w,
            (const float*)d_in[15], (const float*)d_in[16],
            (const float*)d_in[17], (const float*)d_in[18],
            (const float*)d_in[19], (const float*)d_in[20],
            (const float*)d_in[21], (const float*)d_in[22],
            (const float*)d_in[23], (const float*)d_in[24],
            (const float*)d_in[25], (const float*)d_in[26]);
    }
    to_nhwc_half<<<dim3(475, 8, 10), dim3(32, 32)>>>(feats[0], feats[1], feats[2],
                                                     feats[3], feats[4], xh);

    // fork: reg chain on s1
    cudaEventRecord(eF, 0);
    cudaStreamWaitEvent(s1, eF, 0);

    int gApplyX = (TOTE / 4 + 255) / 256;

    // --- cls chain (default stream) ---
    {
        const __half* cur = xh;
        __half* cd[4] = {actA, actB, actA, actB};
        for (int s = 0; s < 4; s++) {
            gemm16<<<dim3(NTILES, 2), 256, DYN_SMEM>>>(
                cur, wtc + (size_t)s * 589824, cls_conv_b + s * 256, ybuf,
                gsum + s * 640, gsq + s * 640, 72, 0, 0);
            gn_coef<<<2, 160>>>(gsum + s * 640, gsq + s * 640,
                                cls_gn_w + s * 256, cls_gn_b + s * 256, scl, shf);
            gn_apply<<<gApplyX, 256>>>(ybuf, cd[s], scl, shf);
            cur = cd[s];
        }
        gemm16<<<dim3(NTILES, 1), 256, DYN_SMEM>>>(actB, wtco, cls_out_b, out,
                                                   nullptr, nullptr, 72, 1, 0);
    }

    // --- reg chain (s1) ---
    {
        const __half* cur = xh;
        __half* rd[4] = {actC, actD, actC, actD};
        for (int s = 0; s < 4; s++) {
            gemm16<<<dim3(NTILES, 2), 256, DYN_SMEM, s1>>>(
                cur, wtr + (size_t)s * 589824, reg_conv_b + s * 256, ybuf2,
                gsum + s * 640 + 320, gsq + s * 640 + 320, 72, 0, 1);
            gn_coef<<<2, 160, 0, s1>>>(gsum + s * 640 + 320, gsq + s * 640 + 320,
                                       reg_gn_w + s * 256, reg_gn_b + s * 256,
                                       scl + 2560, shf + 2560);
            gn_apply<<<gApplyX, 256, 0, s1>>>(ybuf2, rd[s], scl + 2560, shf + 2560);
            cur = rd[s];
        }
        gemm16<<<dim3(NTILES, 1), 256, DYN_SMEM, s1>>>(actD, wtro, regb, out,
                                                       nullptr, nullptr, 72, 1, 1);
    }

    // join
    cudaEventRecord(eJ, s1);
    cudaStreamWaitEvent(0, eJ, 0);

    (void)in_sizes; (void)n_in; (void)out_size;
}